// round 1
// baseline (speedup 1.0000x reference)
#include <cuda_runtime.h>
#include <math.h>

#define FULLMASK 0xffffffffu

// Problem sizes
#define BB   64
#define HPP  64
#define HH   64
#define WW   64
#define DDIM 32
#define NROW (BB * HPP)   // 4096 rows
#define NEL  (HH * WW)    // 4096 elements per row

// ---------------- device scratch (no allocations allowed) ----------------
__device__ float g_feat[NROW * DDIM];   // 0.5 MB
__device__ float g_gate[NROW];
__device__ float g_row [NROW * HH];
__device__ float g_col [NROW * WW];
__device__ float g_drow[NROW * HH];
__device__ float g_dcol[NROW * WW];

// ---------------- warp reduction helpers ----------------
__device__ __forceinline__ float wsum(float v) {
#pragma unroll
    for (int m = 16; m > 0; m >>= 1) v += __shfl_xor_sync(FULLMASK, v, m);
    return v;
}
__device__ __forceinline__ float wmax(float v) {
#pragma unroll
    for (int m = 16; m > 0; m >>= 1) v = fmaxf(v, __shfl_xor_sync(FULLMASK, v, m));
    return v;
}
__device__ __forceinline__ float wmin(float v) {
#pragma unroll
    for (int m = 16; m > 0; m >>= 1) v = fminf(v, __shfl_xor_sync(FULLMASK, v, m));
    return v;
}

// =====================================================================
// Kernel 1: per-row stats over 4096 elems of a,b  ->  12 stats -> feat
// One warp per (b,hp) row. 512 blocks x 256 threads (8 warps/block).
// =====================================================================
__global__ void k_stats_feat(const float* __restrict__ a,
                             const float* __restrict__ b,
                             const float* __restrict__ layer_emb,
                             const float* __restrict__ ipw,   // [32][12]
                             const float* __restrict__ ipb)   // [32]
{
    const int warp = threadIdx.x >> 5;
    const int lane = threadIdx.x & 31;
    const int row  = (blockIdx.x << 3) + warp;   // < 4096

    const float4* ap = reinterpret_cast<const float4*>(a) + (size_t)row * (NEL / 4);
    const float4* bp = reinterpret_cast<const float4*>(b) + (size_t)row * (NEL / 4);

    float sa = 0.f, sa2 = 0.f, sb = 0.f, sb2 = 0.f, sab = 0.f;
    float mna =  3.4e38f, mxa = -3.4e38f;
    float mnb =  3.4e38f, mxb = -3.4e38f;

#pragma unroll 4
    for (int i = lane; i < NEL / 4; i += 32) {
        float4 x = ap[i];
        float4 y = bp[i];
#define ACC(c) { float xa = x.c, xb = y.c;                                 \
                 sa += xa; sa2 = fmaf(xa, xa, sa2);                        \
                 sb += xb; sb2 = fmaf(xb, xb, sb2);                        \
                 sab = fmaf(xa, xb, sab);                                  \
                 mna = fminf(mna, xa); mxa = fmaxf(mxa, xa);               \
                 mnb = fminf(mnb, xb); mxb = fmaxf(mxb, xb); }
        ACC(x) ACC(y) ACC(z) ACC(w)
#undef ACC
    }

    sa  = wsum(sa);  sa2 = wsum(sa2);
    sb  = wsum(sb);  sb2 = wsum(sb2);
    sab = wsum(sab);
    mna = wmin(mna); mxa = wmax(mxa);
    mnb = wmin(mnb); mxb = wmax(mxb);

    const float iN   = 1.f / 4096.f;
    const float iNm1 = 1.f / 4095.f;

    const float mean_a = sa * iN;
    const float mean_b = sb * iN;
    const float va  = fmaxf(sa2 - sa * sa * iN, 0.f) * iNm1;
    const float vb  = fmaxf(sb2 - sb * sb * iN, 0.f) * iNm1;
    const float na  = sqrtf(sa2);
    const float nb  = sqrtf(sb2);
    const float sd  = sa - sb;
    const float sd2 = fmaxf(sa2 - 2.f * sab + sb2, 0.f);
    const float vd  = fmaxf(sd2 - sd * sd * iN, 0.f) * iNm1;

    float st[12];
    st[0]  = mean_a;       st[1]  = sqrtf(va);
    st[2]  = mna;          st[3]  = mxa;
    st[4]  = mean_b;       st[5]  = sqrtf(vb);
    st[6]  = mnb;          st[7]  = mxb;
    st[8]  = sd * iN;      st[9]  = sqrtf(vd);
    st[10] = sqrtf(sd2);
    st[11] = sab / (fmaxf(na, 1e-8f) * fmaxf(nb, 1e-8f));

    // feat[d] = stats . ipw[d,:] + ipb[d] + layer_emb[d]   (lane = d)
    float f = ipb[lane] + layer_emb[lane];
#pragma unroll
    for (int k = 0; k < 12; k++) f = fmaf(st[k], ipw[lane * 12 + k], f);
    g_feat[row * DDIM + lane] = f;
}

// =====================================================================
// Kernel 2: per-batch cross-head attention. 64 blocks x 256 threads.
// Dynamic smem layout (floats):
//   s_feat [64][33] @ 0      (2112)
//   s_x    [64][33] @ 2112   (2112)  -- x for LN1/qkv, later reused for ao
//   s_qkv  [64][97] @ 4224   (6208)
//   s_attn [2][64][64] @ 10432 (8192)
// total 18624 floats = 74496 B
// =====================================================================
__global__ void k_attn(const float* __restrict__ ln1_g, const float* __restrict__ ln1_b,
                       const float* __restrict__ qkv_w, const float* __restrict__ qkv_b,
                       const float* __restrict__ out_w, const float* __restrict__ out_b)
{
    extern __shared__ float sm[];
    float* s_feat = sm;                 // [64][33]
    float* s_x    = sm + 2112;          // [64][33] (x, then ao)
    float* s_qkv  = sm + 4224;          // [64][97]
    float* s_attn = sm + 10432;         // [2][64][64]

    const int tid  = threadIdx.x;
    const int warp = tid >> 5;
    const int lane = tid & 31;
    const int rbase = blockIdx.x * 64;

    // 1. load feat tile
    for (int idx = tid; idx < 64 * 32; idx += 256)
        s_feat[(idx >> 5) * 33 + (idx & 31)] = g_feat[rbase * 32 + idx];
    __syncthreads();

    // 2. LN1 -> s_x   (warp per row, lane = d)
    for (int r = warp; r < 64; r += 8) {
        float v  = s_feat[r * 33 + lane];
        float mu = wsum(v) * (1.f / 32.f);
        float d  = v - mu;
        float var = wsum(d * d) * (1.f / 32.f);
        float rs  = rsqrtf(var + 1e-5f);
        s_x[r * 33 + lane] = d * rs * ln1_g[lane] + ln1_b[lane];
    }
    __syncthreads();

    // 3. qkv = x @ Wqkv^T + b   (e warp-uniform -> weight broadcast)
    for (int idx = tid; idx < 64 * 96; idx += 256) {
        int e = idx >> 6, hp = idx & 63;
        float acc = qkv_b[e];
#pragma unroll
        for (int d = 0; d < 32; d++)
            acc = fmaf(s_x[hp * 33 + d], qkv_w[e * 32 + d], acc);
        s_qkv[hp * 97 + e] = acc;
    }
    __syncthreads();

    // 4. scores[h][q][k] = (q . k) / 4
    for (int idx = tid; idx < 2 * 64 * 64; idx += 256) {
        int k = idx & 63, q = (idx >> 6) & 63, h = idx >> 12;
        const float* qp = &s_qkv[q * 97 + h * 16];
        const float* kp = &s_qkv[k * 97 + 32 + h * 16];
        float acc = 0.f;
#pragma unroll
        for (int dh = 0; dh < 16; dh++) acc = fmaf(qp[dh], kp[dh], acc);
        s_attn[idx] = acc * 0.25f;
    }
    __syncthreads();

    // 5. softmax over k (128 rows, warp per row; lane holds k, k+32)
    for (int r = warp; r < 128; r += 8) {
        float* sr = &s_attn[r * 64];
        float s0 = sr[lane], s1 = sr[lane + 32];
        float M  = wmax(fmaxf(s0, s1));
        float e0 = __expf(s0 - M), e1 = __expf(s1 - M);
        float Z  = wsum(e0 + e1);
        float inv = 1.f / Z;
        sr[lane] = e0 * inv; sr[lane + 32] = e1 * inv;
    }
    __syncthreads();

    // 6. ao[hp][d] = sum_k attn[h][hp][k] * v[k][d]  (warp per hp, lane = d)
    //    x is dead; write ao into s_x.
    for (int hp = warp; hp < 64; hp += 8) {
        int h = lane >> 4;
        const float* ar = &s_attn[(h << 12) + hp * 64];
        float acc = 0.f;
#pragma unroll
        for (int k = 0; k < 64; k++)
            acc = fmaf(ar[k], s_qkv[k * 97 + 64 + lane], acc);
        s_x[hp * 33 + lane] = acc;
    }
    __syncthreads();

    // 7. out proj + residual -> g_feat (in place)
    for (int idx = tid; idx < 64 * 32; idx += 256) {
        int d = idx >> 6, hp = idx & 63;
        float acc = out_b[d];
#pragma unroll
        for (int e = 0; e < 32; e++)
            acc = fmaf(s_x[hp * 33 + e], out_w[d * 32 + e], acc);
        g_feat[(rbase + hp) * 32 + d] = s_feat[hp * 33 + d] + acc;
    }
}

// =====================================================================
// Kernel 3: LN2 + FFN + heads. Block = 32 rows. 128 blocks x 256 threads.
// =====================================================================
__device__ __forceinline__ void head64(const float* __restrict__ w,
                                       const float* __restrict__ bia,
                                       float* __restrict__ gout,
                                       const float* s_f, float* s_o,
                                       int rbase, int tid)
{
    for (int idx = tid; idx < 64 * 32; idx += 256) {
        int i = idx >> 5, r = idx & 31;
        float acc = bia[i];
#pragma unroll
        for (int d = 0; d < 32; d++)
            acc = fmaf(s_f[r * 33 + d], w[i * 32 + d], acc);
        s_o[r * 65 + i] = acc;
    }
    __syncthreads();
    for (int idx = tid; idx < 64 * 32; idx += 256) {
        int r = idx >> 6, i = idx & 63;
        gout[(rbase + r) * 64 + i] = s_o[r * 65 + i];
    }
    __syncthreads();
}

__global__ void k_ffn_heads(const float* __restrict__ ln2_g, const float* __restrict__ ln2_b,
                            const float* __restrict__ w1, const float* __restrict__ b1,
                            const float* __restrict__ w2, const float* __restrict__ b2,
                            const float* __restrict__ gate_w, const float* __restrict__ gate_b,
                            const float* __restrict__ row_w, const float* __restrict__ row_b,
                            const float* __restrict__ col_w, const float* __restrict__ col_b,
                            const float* __restrict__ drow_w, const float* __restrict__ drow_b,
                            const float* __restrict__ dcol_w, const float* __restrict__ dcol_b)
{
    __shared__ float s_f[32 * 33];
    __shared__ float s_y[32 * 33];
    __shared__ float s_h[32 * 65];
    __shared__ float s_o[32 * 65];

    const int tid  = threadIdx.x;
    const int warp = tid >> 5;
    const int lane = tid & 31;
    const int rbase = blockIdx.x * 32;

    for (int idx = tid; idx < 32 * 32; idx += 256)
        s_f[(idx >> 5) * 33 + (idx & 31)] = g_feat[rbase * 32 + idx];
    __syncthreads();

    // LN2
    for (int r = warp; r < 32; r += 8) {
        float v  = s_f[r * 33 + lane];
        float mu = wsum(v) * (1.f / 32.f);
        float d  = v - mu;
        float var = wsum(d * d) * (1.f / 32.f);
        s_y[r * 33 + lane] = d * rsqrtf(var + 1e-5f) * ln2_g[lane] + ln2_b[lane];
    }
    __syncthreads();

    // FFN1 + exact GELU
    for (int idx = tid; idx < 64 * 32; idx += 256) {
        int f = idx >> 5, r = idx & 31;
        float acc = b1[f];
#pragma unroll
        for (int d = 0; d < 32; d++)
            acc = fmaf(s_y[r * 33 + d], w1[f * 32 + d], acc);
        s_h[r * 65 + f] = 0.5f * acc * (1.f + erff(acc * 0.70710678118654752f));
    }
    __syncthreads();

    // FFN2 + residual
    for (int idx = tid; idx < 32 * 32; idx += 256) {
        int d = idx >> 5, r = idx & 31;
        float acc = b2[d];
#pragma unroll
        for (int f = 0; f < 64; f++)
            acc = fmaf(s_h[r * 65 + f], w2[d * 64 + f], acc);
        s_f[r * 33 + d] += acc;
    }
    __syncthreads();

    // gate head
    if (tid < 32) {
        int r = tid;
        float acc = gate_b[0];
#pragma unroll
        for (int d = 0; d < 32; d++)
            acc = fmaf(s_f[r * 33 + d], gate_w[d], acc);
        g_gate[rbase + r] = acc;
    }

    // row/col/drow/dcol heads (staged -> coalesced)
    head64(row_w,  row_b,  g_row,  s_f, s_o, rbase, tid);
    head64(col_w,  col_b,  g_col,  s_f, s_o, rbase, tid);
    head64(drow_w, drow_b, g_drow, s_f, s_o, rbase, tid);
    head64(dcol_w, dcol_b, g_dcol, s_f, s_o, rbase, tid);
}

// =====================================================================
// Kernel 4: merge. Block per (b,hp): 4096 blocks x 256 threads.
// sigmoid(g + r_i + c_j) factored: E = exp(g+r_i) * exp(c_j)
// -> 128 exps/block instead of 4096; 1 MUFU (rcp) per element.
// =====================================================================
__global__ void k_merge(const float* __restrict__ a,
                        const float* __restrict__ b,
                        const float* __restrict__ ds_p,
                        float* __restrict__ out)
{
    __shared__ float sA[64], sC[64], sDr[64], sDc[64];
    const int blk = blockIdx.x;
    const int t   = threadIdx.x;

    if (t < 64) {
        float g  = g_gate[blk];
        float rv = g + g_row[blk * 64 + t];
        float cv = g_col[blk * 64 + t];
        rv = fminf(fmaxf(rv, -25.f), 25.f);   // clamp only affects saturated sigmoid
        cv = fminf(fmaxf(cv, -25.f), 25.f);
        sA[t]  = __expf(rv);
        sC[t]  = __expf(cv);
        sDr[t] = ds_p[0] * g_drow[blk * 64 + t];
        sDc[t] = g_dcol[blk * 64 + t];
    }
    __syncthreads();

    const float4* ap = reinterpret_cast<const float4*>(a) + (size_t)blk * 1024;
    const float4* bp = reinterpret_cast<const float4*>(b) + (size_t)blk * 1024;
    float4*       op = reinterpret_cast<float4*>(out)     + (size_t)blk * 1024;

#pragma unroll
    for (int rep = 0; rep < 4; rep++) {
        int f = t + rep * 256;
        float4 av = ap[f];
        float4 bv = bp[f];
        int i  = f >> 4;
        int jb = (f & 15) << 2;
        float Ai  = sA[i];
        float dri = sDr[i];
        float4 o;
#define MERGE(c, jj) {                                                     \
            float E = Ai * sC[jj];                                          \
            float m = __fdividef(E, 1.f + E);                               \
            o.c = fmaf(m, av.c - bv.c, fmaf(dri, sDc[jj], bv.c)); }
        MERGE(x, jb + 0) MERGE(y, jb + 1) MERGE(z, jb + 2) MERGE(w, jb + 3)
#undef MERGE
        op[f] = o;
    }
}

// =====================================================================
// launcher
// =====================================================================
extern "C" void kernel_launch(void* const* d_in, const int* in_sizes, int n_in,
                              void* d_out, int out_size)
{
    const float* a           = (const float*)d_in[0];
    const float* b           = (const float*)d_in[1];
    const float* layer_emb   = (const float*)d_in[2];
    const float* in_proj_w   = (const float*)d_in[3];
    const float* in_proj_b   = (const float*)d_in[4];
    const float* ln1_g       = (const float*)d_in[5];
    const float* ln1_b       = (const float*)d_in[6];
    const float* qkv_w       = (const float*)d_in[7];
    const float* qkv_b       = (const float*)d_in[8];
    const float* out_w       = (const float*)d_in[9];
    const float* out_b       = (const float*)d_in[10];
    const float* ln2_g       = (const float*)d_in[11];
    const float* ln2_b       = (const float*)d_in[12];
    const float* ffn_w1      = (const float*)d_in[13];
    const float* ffn_b1      = (const float*)d_in[14];
    const float* ffn_w2      = (const float*)d_in[15];
    const float* ffn_b2      = (const float*)d_in[16];
    const float* gate_w      = (const float*)d_in[17];
    const float* gate_b      = (const float*)d_in[18];
    const float* row_w       = (const float*)d_in[19];
    const float* row_b       = (const float*)d_in[20];
    const float* col_w       = (const float*)d_in[21];
    const float* col_b       = (const float*)d_in[22];
    const float* drow_w      = (const float*)d_in[23];
    const float* drow_b      = (const float*)d_in[24];
    const float* dcol_w      = (const float*)d_in[25];
    const float* dcol_b      = (const float*)d_in[26];
    const float* delta_scale = (const float*)d_in[27];
    float* out = (float*)d_out;

    const int attn_smem = 18624 * 4;   // 74496 B dynamic
    cudaFuncSetAttribute(k_attn, cudaFuncAttributeMaxDynamicSharedMemorySize, attn_smem);

    k_stats_feat<<<512, 256>>>(a, b, layer_emb, in_proj_w, in_proj_b);
    k_attn<<<64, 256, attn_smem>>>(ln1_g, ln1_b, qkv_w, qkv_b, out_w, out_b);
    k_ffn_heads<<<128, 256>>>(ln2_g, ln2_b, ffn_w1, ffn_b1, ffn_w2, ffn_b2,
                              gate_w, gate_b, row_w, row_b, col_w, col_b,
                              drow_w, drow_b, dcol_w, dcol_b);
    k_merge<<<4096, 256>>>(a, b, delta_scale, out);
}

// round 2
// speedup vs baseline: 1.0348x; 1.0348x over previous
#include <cuda_runtime.h>
#include <cuda_fp16.h>
#include <math.h>

#define FULLMASK 0xffffffffu

// Problem sizes
#define BB   64
#define HPP  64
#define HH   64
#define WW   64
#define DDIM 32
#define NROW (BB * HPP)   // 4096 rows
#define NEL  (HH * WW)    // 4096 elements per row

typedef unsigned long long ull;

// ---------------- device scratch (no allocations allowed) ----------------
__device__ float g_feat[NROW * DDIM];   // 0.5 MB
__device__ float g_gate[NROW];
__device__ float g_row [NROW * HH];
__device__ float g_col [NROW * WW];
__device__ float g_drow[NROW * HH];
__device__ float g_dcol[NROW * WW];

// ---------------- packed f32x2 helpers (Blackwell 2x fp32 path) ----------
__device__ __forceinline__ void fadd2(ull& acc, ull v) {
    asm("add.rn.f32x2 %0, %0, %1;" : "+l"(acc) : "l"(v));
}
__device__ __forceinline__ void ffma2(ull& acc, ull x, ull y) {
    asm("fma.rn.f32x2 %0, %1, %2, %0;" : "+l"(acc) : "l"(x), "l"(y));
}
__device__ __forceinline__ void unpack2(ull v, float& lo, float& hi) {
    asm("mov.b64 {%0, %1}, %2;" : "=f"(lo), "=f"(hi) : "l"(v));
}
__device__ __forceinline__ float red2(ull v) {
    float lo, hi; unpack2(v, lo, hi); return lo + hi;
}

// ---------------- packed f16x2 min/max helpers ----------------
__device__ __forceinline__ unsigned cvt2h(float x, float y) {
    unsigned r; asm("cvt.rn.f16x2.f32 %0, %1, %2;" : "=r"(r) : "f"(x), "f"(y));
    return r;
}
__device__ __forceinline__ void hmin2(unsigned& acc, unsigned v) {
    asm("min.f16x2 %0, %0, %1;" : "+r"(acc) : "r"(v));
}
__device__ __forceinline__ void hmax2(unsigned& acc, unsigned v) {
    asm("max.f16x2 %0, %0, %1;" : "+r"(acc) : "r"(v));
}
__device__ __forceinline__ unsigned umin2(unsigned a, unsigned b) {
    unsigned r; asm("min.f16x2 %0, %1, %2;" : "=r"(r) : "r"(a), "r"(b)); return r;
}
__device__ __forceinline__ unsigned umax2(unsigned a, unsigned b) {
    unsigned r; asm("max.f16x2 %0, %1, %2;" : "=r"(r) : "r"(a), "r"(b)); return r;
}

// ---------------- warp reduction helpers ----------------
__device__ __forceinline__ float wsum(float v) {
#pragma unroll
    for (int m = 16; m > 0; m >>= 1) v += __shfl_xor_sync(FULLMASK, v, m);
    return v;
}
__device__ __forceinline__ float wmax(float v) {
#pragma unroll
    for (int m = 16; m > 0; m >>= 1) v = fmaxf(v, __shfl_xor_sync(FULLMASK, v, m));
    return v;
}

// =====================================================================
// Kernel 1: per-row stats over 4096 elems of a,b  ->  12 stats -> feat
// One warp per (b,hp) row. 512 blocks x 256 threads (8 warps/block).
// Sums via packed f32x2 FADD/FFMA; min/max via packed f16x2 HMNMX2.
// =====================================================================
__global__ void k_stats_feat(const float* __restrict__ a,
                             const float* __restrict__ b,
                             const float* __restrict__ layer_emb,
                             const float* __restrict__ ipw,   // [32][12]
                             const float* __restrict__ ipb)   // [32]
{
    const int warp = threadIdx.x >> 5;
    const int lane = threadIdx.x & 31;
    const int row  = (blockIdx.x << 3) + warp;   // < 4096

    const ulonglong2* ap = reinterpret_cast<const ulonglong2*>(a) + (size_t)row * (NEL / 4);
    const ulonglong2* bp = reinterpret_cast<const ulonglong2*>(b) + (size_t)row * (NEL / 4);

    ull saP = 0, saQ = 0, aaP = 0, aaQ = 0;
    ull sbP = 0, sbQ = 0, bbP = 0, bbQ = 0;
    ull abP = 0, abQ = 0;
    unsigned mnA = 0x7C007C00u, mxA = 0xFC00FC00u;   // +inf/-inf f16x2
    unsigned mnB = 0x7C007C00u, mxB = 0xFC00FC00u;

#pragma unroll 4
    for (int i = lane; i < NEL / 4; i += 32) {
        ulonglong2 A = ap[i];
        ulonglong2 B = bp[i];

        // packed sums: 10 f32x2 ops covering 4 element-pairs
        fadd2(saP, A.x); ffma2(aaP, A.x, A.x);
        fadd2(saQ, A.y); ffma2(aaQ, A.y, A.y);
        fadd2(sbP, B.x); ffma2(bbP, B.x, B.x);
        fadd2(sbQ, B.y); ffma2(bbQ, B.y, B.y);
        ffma2(abP, A.x, B.x); ffma2(abQ, A.y, B.y);

        // packed f16 min/max
        float a0, a1, a2, a3, b0, b1, b2, b3;
        unpack2(A.x, a0, a1); unpack2(A.y, a2, a3);
        unpack2(B.x, b0, b1); unpack2(B.y, b2, b3);
        unsigned ha01 = cvt2h(a0, a1), ha23 = cvt2h(a2, a3);
        unsigned hb01 = cvt2h(b0, b1), hb23 = cvt2h(b2, b3);
        hmin2(mnA, ha01); hmin2(mnA, ha23);
        hmax2(mxA, ha01); hmax2(mxA, ha23);
        hmin2(mnB, hb01); hmin2(mnB, hb23);
        hmax2(mxB, hb01); hmax2(mxB, hb23);
    }

    float sa  = red2(saP) + red2(saQ);
    float sa2 = red2(aaP) + red2(aaQ);
    float sb  = red2(sbP) + red2(sbQ);
    float sb2 = red2(bbP) + red2(bbQ);
    float sab = red2(abP) + red2(abQ);

    sa  = wsum(sa);  sa2 = wsum(sa2);
    sb  = wsum(sb);  sb2 = wsum(sb2);
    sab = wsum(sab);

#pragma unroll
    for (int m = 16; m > 0; m >>= 1) {
        mnA = umin2(mnA, __shfl_xor_sync(FULLMASK, mnA, m));
        mxA = umax2(mxA, __shfl_xor_sync(FULLMASK, mxA, m));
        mnB = umin2(mnB, __shfl_xor_sync(FULLMASK, mnB, m));
        mxB = umax2(mxB, __shfl_xor_sync(FULLMASK, mxB, m));
    }
    __half2 hmnA = *reinterpret_cast<const __half2*>(&mnA);
    __half2 hmxA = *reinterpret_cast<const __half2*>(&mxA);
    __half2 hmnB = *reinterpret_cast<const __half2*>(&mnB);
    __half2 hmxB = *reinterpret_cast<const __half2*>(&mxB);
    const float mna = fminf(__low2float(hmnA), __high2float(hmnA));
    const float mxa = fmaxf(__low2float(hmxA), __high2float(hmxA));
    const float mnb = fminf(__low2float(hmnB), __high2float(hmnB));
    const float mxb = fmaxf(__low2float(hmxB), __high2float(hmxB));

    const float iN   = 1.f / 4096.f;
    const float iNm1 = 1.f / 4095.f;

    const float va  = fmaxf(sa2 - sa * sa * iN, 0.f) * iNm1;
    const float vb  = fmaxf(sb2 - sb * sb * iN, 0.f) * iNm1;
    const float na  = sqrtf(sa2);
    const float nb  = sqrtf(sb2);
    const float sd  = sa - sb;
    const float sd2 = fmaxf(sa2 - 2.f * sab + sb2, 0.f);
    const float vd  = fmaxf(sd2 - sd * sd * iN, 0.f) * iNm1;

    float st[12];
    st[0]  = sa * iN;      st[1]  = sqrtf(va);
    st[2]  = mna;          st[3]  = mxa;
    st[4]  = sb * iN;      st[5]  = sqrtf(vb);
    st[6]  = mnb;          st[7]  = mxb;
    st[8]  = sd * iN;      st[9]  = sqrtf(vd);
    st[10] = sqrtf(sd2);
    st[11] = sab / (fmaxf(na, 1e-8f) * fmaxf(nb, 1e-8f));

    // feat[d] = stats . ipw[d,:] + ipb[d] + layer_emb[d]   (lane = d)
    float f = ipb[lane] + layer_emb[lane];
#pragma unroll
    for (int k = 0; k < 12; k++) f = fmaf(st[k], ipw[lane * 12 + k], f);
    g_feat[row * DDIM + lane] = f;
}

// =====================================================================
// Kernel 2: per-batch cross-head attention. 64 blocks x 256 threads.
// =====================================================================
__global__ void k_attn(const float* __restrict__ ln1_g, const float* __restrict__ ln1_b,
                       const float* __restrict__ qkv_w, const float* __restrict__ qkv_b,
                       const float* __restrict__ out_w, const float* __restrict__ out_b)
{
    extern __shared__ float sm[];
    float* s_feat = sm;                 // [64][33]
    float* s_x    = sm + 2112;          // [64][33] (x, then ao)
    float* s_qkv  = sm + 4224;          // [64][97]
    float* s_attn = sm + 10432;         // [2][64][64]

    const int tid  = threadIdx.x;
    const int warp = tid >> 5;
    const int lane = tid & 31;
    const int rbase = blockIdx.x * 64;

    for (int idx = tid; idx < 64 * 32; idx += 256)
        s_feat[(idx >> 5) * 33 + (idx & 31)] = g_feat[rbase * 32 + idx];
    __syncthreads();

    for (int r = warp; r < 64; r += 8) {
        float v  = s_feat[r * 33 + lane];
        float mu = wsum(v) * (1.f / 32.f);
        float d  = v - mu;
        float var = wsum(d * d) * (1.f / 32.f);
        float rs  = rsqrtf(var + 1e-5f);
        s_x[r * 33 + lane] = d * rs * ln1_g[lane] + ln1_b[lane];
    }
    __syncthreads();

    for (int idx = tid; idx < 64 * 96; idx += 256) {
        int e = idx >> 6, hp = idx & 63;
        float acc = qkv_b[e];
#pragma unroll
        for (int d = 0; d < 32; d++)
            acc = fmaf(s_x[hp * 33 + d], qkv_w[e * 32 + d], acc);
        s_qkv[hp * 97 + e] = acc;
    }
    __syncthreads();

    for (int idx = tid; idx < 2 * 64 * 64; idx += 256) {
        int k = idx & 63, q = (idx >> 6) & 63, h = idx >> 12;
        const float* qp = &s_qkv[q * 97 + h * 16];
        const float* kp = &s_qkv[k * 97 + 32 + h * 16];
        float acc = 0.f;
#pragma unroll
        for (int dh = 0; dh < 16; dh++) acc = fmaf(qp[dh], kp[dh], acc);
        s_attn[idx] = acc * 0.25f;
    }
    __syncthreads();

    for (int r = warp; r < 128; r += 8) {
        float* sr = &s_attn[r * 64];
        float s0 = sr[lane], s1 = sr[lane + 32];
        float M  = wmax(fmaxf(s0, s1));
        float e0 = __expf(s0 - M), e1 = __expf(s1 - M);
        float Z  = wsum(e0 + e1);
        float inv = 1.f / Z;
        sr[lane] = e0 * inv; sr[lane + 32] = e1 * inv;
    }
    __syncthreads();

    for (int hp = warp; hp < 64; hp += 8) {
        int h = lane >> 4;
        const float* ar = &s_attn[(h << 12) + hp * 64];
        float acc = 0.f;
#pragma unroll
        for (int k = 0; k < 64; k++)
            acc = fmaf(ar[k], s_qkv[k * 97 + 64 + lane], acc);
        s_x[hp * 33 + lane] = acc;
    }
    __syncthreads();

    for (int idx = tid; idx < 64 * 32; idx += 256) {
        int d = idx >> 6, hp = idx & 63;
        float acc = out_b[d];
#pragma unroll
        for (int e = 0; e < 32; e++)
            acc = fmaf(s_x[hp * 33 + e], out_w[d * 32 + e], acc);
        g_feat[(rbase + hp) * 32 + d] = s_feat[hp * 33 + d] + acc;
    }
}

// =====================================================================
// Kernel 3: LN2 + FFN + heads. Block = 32 rows. 128 blocks x 256 threads.
// =====================================================================
__device__ __forceinline__ void head64(const float* __restrict__ w,
                                       const float* __restrict__ bia,
                                       float* __restrict__ gout,
                                       const float* s_f, float* s_o,
                                       int rbase, int tid)
{
    for (int idx = tid; idx < 64 * 32; idx += 256) {
        int i = idx >> 5, r = idx & 31;
        float acc = bia[i];
#pragma unroll
        for (int d = 0; d < 32; d++)
            acc = fmaf(s_f[r * 33 + d], w[i * 32 + d], acc);
        s_o[r * 65 + i] = acc;
    }
    __syncthreads();
    for (int idx = tid; idx < 64 * 32; idx += 256) {
        int r = idx >> 6, i = idx & 63;
        gout[(rbase + r) * 64 + i] = s_o[r * 65 + i];
    }
    __syncthreads();
}

__global__ void k_ffn_heads(const float* __restrict__ ln2_g, const float* __restrict__ ln2_b,
                            const float* __restrict__ w1, const float* __restrict__ b1,
                            const float* __restrict__ w2, const float* __restrict__ b2,
                            const float* __restrict__ gate_w, const float* __restrict__ gate_b,
                            const float* __restrict__ row_w, const float* __restrict__ row_b,
                            const float* __restrict__ col_w, const float* __restrict__ col_b,
                            const float* __restrict__ drow_w, const float* __restrict__ drow_b,
                            const float* __restrict__ dcol_w, const float* __restrict__ dcol_b)
{
    __shared__ float s_f[32 * 33];
    __shared__ float s_y[32 * 33];
    __shared__ float s_h[32 * 65];
    __shared__ float s_o[32 * 65];

    const int tid  = threadIdx.x;
    const int warp = tid >> 5;
    const int lane = tid & 31;
    const int rbase = blockIdx.x * 32;

    for (int idx = tid; idx < 32 * 32; idx += 256)
        s_f[(idx >> 5) * 33 + (idx & 31)] = g_feat[rbase * 32 + idx];
    __syncthreads();

    for (int r = warp; r < 32; r += 8) {
        float v  = s_f[r * 33 + lane];
        float mu = wsum(v) * (1.f / 32.f);
        float d  = v - mu;
        float var = wsum(d * d) * (1.f / 32.f);
        s_y[r * 33 + lane] = d * rsqrtf(var + 1e-5f) * ln2_g[lane] + ln2_b[lane];
    }
    __syncthreads();

    for (int idx = tid; idx < 64 * 32; idx += 256) {
        int f = idx >> 5, r = idx & 31;
        float acc = b1[f];
#pragma unroll
        for (int d = 0; d < 32; d++)
            acc = fmaf(s_y[r * 33 + d], w1[f * 32 + d], acc);
        s_h[r * 65 + f] = 0.5f * acc * (1.f + erff(acc * 0.70710678118654752f));
    }
    __syncthreads();

    for (int idx = tid; idx < 32 * 32; idx += 256) {
        int d = idx >> 5, r = idx & 31;
        float acc = b2[d];
#pragma unroll
        for (int f = 0; f < 64; f++)
            acc = fmaf(s_h[r * 65 + f], w2[d * 64 + f], acc);
        s_f[r * 33 + d] += acc;
    }
    __syncthreads();

    if (tid < 32) {
        int r = tid;
        float acc = gate_b[0];
#pragma unroll
        for (int d = 0; d < 32; d++)
            acc = fmaf(s_f[r * 33 + d], gate_w[d], acc);
        g_gate[rbase + r] = acc;
    }

    head64(row_w,  row_b,  g_row,  s_f, s_o, rbase, tid);
    head64(col_w,  col_b,  g_col,  s_f, s_o, rbase, tid);
    head64(drow_w, drow_b, g_drow, s_f, s_o, rbase, tid);
    head64(dcol_w, dcol_b, g_dcol, s_f, s_o, rbase, tid);
}

// =====================================================================
// Kernel 4: merge. Block per (b,hp): 4096 blocks x 256 threads.
// Streaming loads/stores (no reuse, keep L2 clean).
// =====================================================================
__global__ void k_merge(const float* __restrict__ a,
                        const float* __restrict__ b,
                        const float* __restrict__ ds_p,
                        float* __restrict__ out)
{
    __shared__ float sA[64], sC[64], sDr[64], sDc[64];
    const int blk = blockIdx.x;
    const int t   = threadIdx.x;

    if (t < 64) {
        float g  = g_gate[blk];
        float rv = g + g_row[blk * 64 + t];
        float cv = g_col[blk * 64 + t];
        rv = fminf(fmaxf(rv, -25.f), 25.f);
        cv = fminf(fmaxf(cv, -25.f), 25.f);
        sA[t]  = __expf(rv);
        sC[t]  = __expf(cv);
        sDr[t] = ds_p[0] * g_drow[blk * 64 + t];
        sDc[t] = g_dcol[blk * 64 + t];
    }
    __syncthreads();

    const float4* ap = reinterpret_cast<const float4*>(a) + (size_t)blk * 1024;
    const float4* bp = reinterpret_cast<const float4*>(b) + (size_t)blk * 1024;
    float4*       op = reinterpret_cast<float4*>(out)     + (size_t)blk * 1024;

#pragma unroll
    for (int rep = 0; rep < 4; rep++) {
        int f = t + rep * 256;
        float4 av = __ldcs(ap + f);
        float4 bv = __ldcs(bp + f);
        int i  = f >> 4;
        int jb = (f & 15) << 2;
        float Ai  = sA[i];
        float dri = sDr[i];
        float4 o;
#define MERGE(c, jj) {                                                     \
            float E = Ai * sC[jj];                                          \
            float m = __fdividef(E, 1.f + E);                               \
            o.c = fmaf(m, av.c - bv.c, fmaf(dri, sDc[jj], bv.c)); }
        MERGE(x, jb + 0) MERGE(y, jb + 1) MERGE(z, jb + 2) MERGE(w, jb + 3)
#undef MERGE
        __stcs(op + f, o);
    }
}

// =====================================================================
// launcher
// =====================================================================
extern "C" void kernel_launch(void* const* d_in, const int* in_sizes, int n_in,
                              void* d_out, int out_size)
{
    const float* a           = (const float*)d_in[0];
    const float* b           = (const float*)d_in[1];
    const float* layer_emb   = (const float*)d_in[2];
    const float* in_proj_w   = (const float*)d_in[3];
    const float* in_proj_b   = (const float*)d_in[4];
    const float* ln1_g       = (const float*)d_in[5];
    const float* ln1_b       = (const float*)d_in[6];
    const float* qkv_w       = (const float*)d_in[7];
    const float* qkv_b       = (const float*)d_in[8];
    const float* out_w       = (const float*)d_in[9];
    const float* out_b       = (const float*)d_in[10];
    const float* ln2_g       = (const float*)d_in[11];
    const float* ln2_b       = (const float*)d_in[12];
    const float* ffn_w1      = (const float*)d_in[13];
    const float* ffn_b1      = (const float*)d_in[14];
    const float* ffn_w2      = (const float*)d_in[15];
    const float* ffn_b2      = (const float*)d_in[16];
    const float* gate_w      = (const float*)d_in[17];
    const float* gate_b      = (const float*)d_in[18];
    const float* row_w       = (const float*)d_in[19];
    const float* row_b       = (const float*)d_in[20];
    const float* col_w       = (const float*)d_in[21];
    const float* col_b       = (const float*)d_in[22];
    const float* drow_w      = (const float*)d_in[23];
    const float* drow_b      = (const float*)d_in[24];
    const float* dcol_w      = (const float*)d_in[25];
    const float* dcol_b      = (const float*)d_in[26];
    const float* delta_scale = (const float*)d_in[27];
    float* out = (float*)d_out;

    const int attn_smem = 18624 * 4;   // 74496 B dynamic
    cudaFuncSetAttribute(k_attn, cudaFuncAttributeMaxDynamicSharedMemorySize, attn_smem);

    k_stats_feat<<<512, 256>>>(a, b, layer_emb, in_proj_w, in_proj_b);
    k_attn<<<64, 256, attn_smem>>>(ln1_g, ln1_b, qkv_w, qkv_b, out_w, out_b);
    k_ffn_heads<<<128, 256>>>(ln2_g, ln2_b, ffn_w1, ffn_b1, ffn_w2, ffn_b2,
                              gate_w, gate_b, row_w, row_b, col_w, col_b,
                              drow_w, drow_b, dcol_w, dcol_b);
    k_merge<<<4096, 256>>>(a, b, delta_scale, out);
}

// round 5
// speedup vs baseline: 1.3243x; 1.2798x over previous
#include <cuda_runtime.h>
#include <math.h>
#include <float.h>

#define FULLMASK 0xffffffffu

#define BB   64
#define HPP  64
#define HH   64
#define WW   64
#define DDIM 32
#define NROW (BB * HPP)   // 4096
#define NEL  (HH * WW)    // 4096

// ---------------- device scratch ----------------
__device__ float g_feat[NROW * DDIM];
__device__ float g_gate[NROW];
__device__ float g_row [NROW * HH];
__device__ float g_col [NROW * WW];
__device__ float g_drow[NROW * HH];
__device__ float g_dcol[NROW * WW];

// ---------------- warp helpers ----------------
__device__ __forceinline__ float wsum(float v) {
#pragma unroll
    for (int m = 16; m > 0; m >>= 1) v += __shfl_xor_sync(FULLMASK, v, m);
    return v;
}
__device__ __forceinline__ float wmaxr(float v) {
#pragma unroll
    for (int m = 16; m > 0; m >>= 1) v = fmaxf(v, __shfl_xor_sync(FULLMASK, v, m));
    return v;
}
__device__ __forceinline__ float wminr(float v) {
#pragma unroll
    for (int m = 16; m > 0; m >>= 1) v = fminf(v, __shfl_xor_sync(FULLMASK, v, m));
    return v;
}

// =====================================================================
// Kernel 1: block-per-row stats. 4096 blocks x 256 threads.
// Each thread: 8 independent float4 loads (MLP_p1=8), 16 elements.
// =====================================================================
__global__ void __launch_bounds__(256) k_stats_feat(
        const float* __restrict__ a, const float* __restrict__ b,
        const float* __restrict__ layer_emb,
        const float* __restrict__ ipw, const float* __restrict__ ipb)
{
    const int row = blockIdx.x;
    const int t   = threadIdx.x;
    const int warp = t >> 5;
    const int lane = t & 31;

    const float4* ap = reinterpret_cast<const float4*>(a) + (size_t)row * (NEL / 4);
    const float4* bp = reinterpret_cast<const float4*>(b) + (size_t)row * (NEL / 4);

    // 8 independent loads, front-batched
    float4 A0 = ap[t];        float4 A1 = ap[t + 256];
    float4 A2 = ap[t + 512];  float4 A3 = ap[t + 768];
    float4 B0 = bp[t];        float4 B1 = bp[t + 256];
    float4 B2 = bp[t + 512];  float4 B3 = bp[t + 768];

    float sa = 0.f, sa2 = 0.f, sb = 0.f, sb2 = 0.f, sab = 0.f;
    float mna = FLT_MAX, mxa = -FLT_MAX, mnb = FLT_MAX, mxb = -FLT_MAX;

#define ACC(av, bv, c) { float xa = av.c, xb = bv.c;                        \
        sa += xa; sa2 = fmaf(xa, xa, sa2);                                  \
        sb += xb; sb2 = fmaf(xb, xb, sb2);                                  \
        sab = fmaf(xa, xb, sab);                                            \
        mna = fminf(mna, xa); mxa = fmaxf(mxa, xa);                         \
        mnb = fminf(mnb, xb); mxb = fmaxf(mxb, xb); }
#define ACC4(av, bv) ACC(av, bv, x) ACC(av, bv, y) ACC(av, bv, z) ACC(av, bv, w)
    ACC4(A0, B0) ACC4(A1, B1) ACC4(A2, B2) ACC4(A3, B3)
#undef ACC4
#undef ACC

    sa  = wsum(sa);  sa2 = wsum(sa2);
    sb  = wsum(sb);  sb2 = wsum(sb2);
    sab = wsum(sab);
    mna = wminr(mna); mxa = wmaxr(mxa);
    mnb = wminr(mnb); mxb = wmaxr(mxb);

    __shared__ float red[9][8];
    if (lane == 0) {
        red[0][warp] = sa;  red[1][warp] = sa2;
        red[2][warp] = sb;  red[3][warp] = sb2;
        red[4][warp] = sab;
        red[5][warp] = mna; red[6][warp] = mxa;
        red[7][warp] = mnb; red[8][warp] = mxb;
    }
    __syncthreads();

    if (warp == 0) {
        bool ok = lane < 8;
        float v_sa  = ok ? red[0][lane] : 0.f;
        float v_sa2 = ok ? red[1][lane] : 0.f;
        float v_sb  = ok ? red[2][lane] : 0.f;
        float v_sb2 = ok ? red[3][lane] : 0.f;
        float v_sab = ok ? red[4][lane] : 0.f;
        float v_mna = ok ? red[5][lane] :  FLT_MAX;
        float v_mxa = ok ? red[6][lane] : -FLT_MAX;
        float v_mnb = ok ? red[7][lane] :  FLT_MAX;
        float v_mxb = ok ? red[8][lane] : -FLT_MAX;

        v_sa  = wsum(v_sa);  v_sa2 = wsum(v_sa2);
        v_sb  = wsum(v_sb);  v_sb2 = wsum(v_sb2);
        v_sab = wsum(v_sab);
        v_mna = wminr(v_mna); v_mxa = wmaxr(v_mxa);
        v_mnb = wminr(v_mnb); v_mxb = wmaxr(v_mxb);

        const float iN   = 1.f / 4096.f;
        const float iNm1 = 1.f / 4095.f;
        const float va  = fmaxf(v_sa2 - v_sa * v_sa * iN, 0.f) * iNm1;
        const float vb  = fmaxf(v_sb2 - v_sb * v_sb * iN, 0.f) * iNm1;
        const float na  = sqrtf(v_sa2);
        const float nb  = sqrtf(v_sb2);
        const float sd  = v_sa - v_sb;
        const float sd2 = fmaxf(v_sa2 - 2.f * v_sab + v_sb2, 0.f);
        const float vd  = fmaxf(sd2 - sd * sd * iN, 0.f) * iNm1;

        float st[12];
        st[0]  = v_sa * iN;  st[1]  = sqrtf(va);
        st[2]  = v_mna;      st[3]  = v_mxa;
        st[4]  = v_sb * iN;  st[5]  = sqrtf(vb);
        st[6]  = v_mnb;      st[7]  = v_mxb;
        st[8]  = sd * iN;    st[9]  = sqrtf(vd);
        st[10] = sqrtf(sd2);
        st[11] = v_sab / (fmaxf(na, 1e-8f) * fmaxf(nb, 1e-8f));

        float f = ipb[lane] + layer_emb[lane];
#pragma unroll
        for (int k = 0; k < 12; k++) f = fmaf(st[k], ipw[lane * 12 + k], f);
        g_feat[row * DDIM + lane] = f;
    }
}

// =====================================================================
// Kernel 2: fused attn + FFN per batch. 64 blocks x 512 threads.
// feat stays in smem across the whole transformer body.
// s_h aliases s_attn (attn dead after AV product) -> 74496 B dynamic,
// same smem footprint as the R1/R2 kernel that passed on HW.
// =====================================================================
__global__ void __launch_bounds__(512) k_trans(
        const float* __restrict__ ln1_g, const float* __restrict__ ln1_b,
        const float* __restrict__ qkv_w, const float* __restrict__ qkv_b,
        const float* __restrict__ out_w, const float* __restrict__ out_b,
        const float* __restrict__ ln2_g, const float* __restrict__ ln2_b,
        const float* __restrict__ w1, const float* __restrict__ b1,
        const float* __restrict__ w2, const float* __restrict__ b2)
{
    extern __shared__ float sm[];
    float* s_feat = sm;            // [64][33]  2112
    float* s_x    = sm + 2112;     // [64][33]  2112
    float* s_qkv  = sm + 4224;     // [64][97]  6208
    float* s_attn = sm + 10432;    // [2][64][64] 8192
    float* s_h    = sm + 10432;    // [64][65]  4160, ALIASES s_attn (dead)
                                   // total 18624 floats = 74496 B

    const int tid  = threadIdx.x;
    const int warp = tid >> 5;
    const int lane = tid & 31;
    const int rbase = blockIdx.x * 64;

    // load feat
    for (int idx = tid; idx < 64 * 32; idx += 512)
        s_feat[(idx >> 5) * 33 + (idx & 31)] = g_feat[rbase * 32 + idx];
    __syncthreads();

    // LN1
    for (int r = warp; r < 64; r += 16) {
        float v  = s_feat[r * 33 + lane];
        float mu = wsum(v) * (1.f / 32.f);
        float d  = v - mu;
        float var = wsum(d * d) * (1.f / 32.f);
        s_x[r * 33 + lane] = d * rsqrtf(var + 1e-5f) * ln1_g[lane] + ln1_b[lane];
    }
    __syncthreads();

    // QKV with register-cached x row: thread -> (hp = tid&63, group g = tid>>6)
    {
        const int hp = tid & 63;
        const int g  = tid >> 6;          // 0..7
        float xr[32];
#pragma unroll
        for (int d = 0; d < 32; d++) xr[d] = s_x[hp * 33 + d];
#pragma unroll
        for (int c = 0; c < 12; c++) {
            int e = g * 12 + c;           // 0..95
            float acc = qkv_b[e];
#pragma unroll
            for (int d = 0; d < 32; d++)
                acc = fmaf(xr[d], qkv_w[e * 32 + d], acc);
            s_qkv[hp * 97 + e] = acc;
        }
    }
    __syncthreads();

    // scores
    for (int idx = tid; idx < 2 * 64 * 64; idx += 512) {
        int k = idx & 63, q = (idx >> 6) & 63, h = idx >> 12;
        const float* qp = &s_qkv[q * 97 + h * 16];
        const float* kp = &s_qkv[k * 97 + 32 + h * 16];
        float acc = 0.f;
#pragma unroll
        for (int dh = 0; dh < 16; dh++) acc = fmaf(qp[dh], kp[dh], acc);
        s_attn[idx] = acc * 0.25f;
    }
    __syncthreads();

    // softmax
    for (int r = warp; r < 128; r += 16) {
        float* sr = &s_attn[r * 64];
        float s0 = sr[lane], s1 = sr[lane + 32];
        float M  = wmaxr(fmaxf(s0, s1));
        float e0 = __expf(s0 - M), e1 = __expf(s1 - M);
        float inv = 1.f / wsum(e0 + e1);
        sr[lane] = e0 * inv; sr[lane + 32] = e1 * inv;
    }
    __syncthreads();

    // ao -> s_x
    for (int hp = warp; hp < 64; hp += 16) {
        int h = lane >> 4;
        const float* ar = &s_attn[(h << 12) + hp * 64];
        float acc = 0.f;
#pragma unroll
        for (int k = 0; k < 64; k++)
            acc = fmaf(ar[k], s_qkv[k * 97 + 64 + lane], acc);
        s_x[hp * 33 + lane] = acc;
    }
    __syncthreads();

    // out proj + residual (in smem)
    for (int idx = tid; idx < 64 * 32; idx += 512) {
        int d = idx >> 6, hp = idx & 63;
        float acc = out_b[d];
#pragma unroll
        for (int e = 0; e < 32; e++)
            acc = fmaf(s_x[hp * 33 + e], out_w[d * 32 + e], acc);
        s_feat[hp * 33 + d] += acc;
    }
    __syncthreads();

    // LN2 -> s_x
    for (int r = warp; r < 64; r += 16) {
        float v  = s_feat[r * 33 + lane];
        float mu = wsum(v) * (1.f / 32.f);
        float d  = v - mu;
        float var = wsum(d * d) * (1.f / 32.f);
        s_x[r * 33 + lane] = d * rsqrtf(var + 1e-5f) * ln2_g[lane] + ln2_b[lane];
    }
    __syncthreads();

    // FFN1 + exact GELU  (s_attn is dead; s_h aliases it)
    for (int idx = tid; idx < 64 * 64; idx += 512) {
        int f = idx >> 6, r = idx & 63;
        float acc = b1[f];
#pragma unroll
        for (int d = 0; d < 32; d++)
            acc = fmaf(s_x[r * 33 + d], w1[f * 32 + d], acc);
        s_h[r * 65 + f] = 0.5f * acc * (1.f + erff(acc * 0.70710678118654752f));
    }
    __syncthreads();

    // FFN2 + residual
    for (int idx = tid; idx < 64 * 32; idx += 512) {
        int d = idx >> 6, r = idx & 63;
        float acc = b2[d];
#pragma unroll
        for (int f = 0; f < 64; f++)
            acc = fmaf(s_h[r * 65 + f], w2[d * 64 + f], acc);
        s_feat[r * 33 + d] += acc;
    }
    __syncthreads();

    // write final feat
    for (int idx = tid; idx < 64 * 32; idx += 512)
        g_feat[rbase * 32 + idx] = s_feat[(idx >> 5) * 33 + (idx & 31)];
}

// =====================================================================
// Kernel 3: heads. 512 blocks x 256 threads, warp-per-row.
// Weights staged transposed in smem; feat row broadcast via shfl.
// =====================================================================
__global__ void __launch_bounds__(256) k_heads(
        const float* __restrict__ gate_w, const float* __restrict__ gate_b,
        const float* __restrict__ row_w,  const float* __restrict__ row_b,
        const float* __restrict__ col_w,  const float* __restrict__ col_b,
        const float* __restrict__ drow_w, const float* __restrict__ drow_b,
        const float* __restrict__ dcol_w, const float* __restrict__ dcol_b)
{
    __shared__ float s_w[4][32 * 65];   // transposed [d][i], pad 65
    __shared__ float s_bias[4][64];
    __shared__ float s_gw[32];

    const int tid  = threadIdx.x;
    const int warp = tid >> 5;
    const int lane = tid & 31;

    const float* wsrc[4] = { row_w, col_w, drow_w, dcol_w };
    const float* bsrc[4] = { row_b, col_b, drow_b, dcol_b };

    for (int idx = tid; idx < 4 * 64 * 32; idx += 256) {
        int h = idx >> 11, rem = idx & 2047;
        int i = rem >> 5, d = rem & 31;
        s_w[h][d * 65 + i] = wsrc[h][i * 32 + d];
    }
    for (int idx = tid; idx < 256; idx += 256) {
        int h = idx >> 6, i = idx & 63;
        s_bias[h][i] = bsrc[h][i];
    }
    if (tid < 32) s_gw[tid] = gate_w[tid];
    __syncthreads();

    const int rw = blockIdx.x * 8 + warp;  // row, < 4096
    float f = g_feat[rw * 32 + lane];

    float a0 = s_bias[0][lane], a1 = s_bias[0][lane + 32];
    float c0 = s_bias[1][lane], c1 = s_bias[1][lane + 32];
    float p0 = s_bias[2][lane], p1 = s_bias[2][lane + 32];
    float q0 = s_bias[3][lane], q1 = s_bias[3][lane + 32];
    float gacc = 0.f;

#pragma unroll
    for (int d = 0; d < 32; d++) {
        float fd = __shfl_sync(FULLMASK, f, d);
        a0 = fmaf(fd, s_w[0][d * 65 + lane],      a0);
        a1 = fmaf(fd, s_w[0][d * 65 + lane + 32], a1);
        c0 = fmaf(fd, s_w[1][d * 65 + lane],      c0);
        c1 = fmaf(fd, s_w[1][d * 65 + lane + 32], c1);
        p0 = fmaf(fd, s_w[2][d * 65 + lane],      p0);
        p1 = fmaf(fd, s_w[2][d * 65 + lane + 32], p1);
        q0 = fmaf(fd, s_w[3][d * 65 + lane],      q0);
        q1 = fmaf(fd, s_w[3][d * 65 + lane + 32], q1);
        gacc = fmaf(fd, s_gw[d], gacc);
    }

    g_row [rw * 64 + lane] = a0;  g_row [rw * 64 + lane + 32] = a1;
    g_col [rw * 64 + lane] = c0;  g_col [rw * 64 + lane + 32] = c1;
    g_drow[rw * 64 + lane] = p0;  g_drow[rw * 64 + lane + 32] = p1;
    g_dcol[rw * 64 + lane] = q0;  g_dcol[rw * 64 + lane + 32] = q1;
    if (lane == 0) g_gate[rw] = gacc + gate_b[0];
}

// =====================================================================
// Kernel 4: merge (unchanged control). 4096 blocks x 256 threads.
// =====================================================================
__global__ void __launch_bounds__(256) k_merge(
        const float* __restrict__ a, const float* __restrict__ b,
        const float* __restrict__ ds_p, float* __restrict__ out)
{
    __shared__ float sA[64], sC[64], sDr[64], sDc[64];
    const int blk = blockIdx.x;
    const int t   = threadIdx.x;

    if (t < 64) {
        float g  = g_gate[blk];
        float rv = fminf(fmaxf(g + g_row[blk * 64 + t], -25.f), 25.f);
        float cv = fminf(fmaxf(g_col[blk * 64 + t],     -25.f), 25.f);
        sA[t]  = __expf(rv);
        sC[t]  = __expf(cv);
        sDr[t] = ds_p[0] * g_drow[blk * 64 + t];
        sDc[t] = g_dcol[blk * 64 + t];
    }
    __syncthreads();

    const float4* ap = reinterpret_cast<const float4*>(a) + (size_t)blk * 1024;
    const float4* bp = reinterpret_cast<const float4*>(b) + (size_t)blk * 1024;
    float4*       op = reinterpret_cast<float4*>(out)     + (size_t)blk * 1024;

#pragma unroll
    for (int rep = 0; rep < 4; rep++) {
        int f = t + rep * 256;
        float4 av = __ldcs(ap + f);
        float4 bv = __ldcs(bp + f);
        int i  = f >> 4;
        int jb = (f & 15) << 2;
        float Ai  = sA[i];
        float dri = sDr[i];
        float4 o;
#define MERGE(c, jj) {                                                      \
            float E = Ai * sC[jj];                                          \
            float m = __fdividef(E, 1.f + E);                               \
            o.c = fmaf(m, av.c - bv.c, fmaf(dri, sDc[jj], bv.c)); }
        MERGE(x, jb + 0) MERGE(y, jb + 1) MERGE(z, jb + 2) MERGE(w, jb + 3)
#undef MERGE
        __stcs(op + f, o);
    }
}

// =====================================================================
// launcher
// =====================================================================
extern "C" void kernel_launch(void* const* d_in, const int* in_sizes, int n_in,
                              void* d_out, int out_size)
{
    const float* a           = (const float*)d_in[0];
    const float* b           = (const float*)d_in[1];
    const float* layer_emb   = (const float*)d_in[2];
    const float* in_proj_w   = (const float*)d_in[3];
    const float* in_proj_b   = (const float*)d_in[4];
    const float* ln1_g       = (const float*)d_in[5];
    const float* ln1_b       = (const float*)d_in[6];
    const float* qkv_w       = (const float*)d_in[7];
    const float* qkv_b       = (const float*)d_in[8];
    const float* out_w       = (const float*)d_in[9];
    const float* out_b       = (const float*)d_in[10];
    const float* ln2_g       = (const float*)d_in[11];
    const float* ln2_b       = (const float*)d_in[12];
    const float* ffn_w1      = (const float*)d_in[13];
    const float* ffn_b1      = (const float*)d_in[14];
    const float* ffn_w2      = (const float*)d_in[15];
    const float* ffn_b2      = (const float*)d_in[16];
    const float* gate_w      = (const float*)d_in[17];
    const float* gate_b      = (const float*)d_in[18];
    const float* row_w       = (const float*)d_in[19];
    const float* row_b       = (const float*)d_in[20];
    const float* col_w       = (const float*)d_in[21];
    const float* col_b       = (const float*)d_in[22];
    const float* drow_w      = (const float*)d_in[23];
    const float* drow_b      = (const float*)d_in[24];
    const float* dcol_w      = (const float*)d_in[25];
    const float* dcol_b      = (const float*)d_in[26];
    const float* delta_scale = (const float*)d_in[27];
    float* out = (float*)d_out;

    const int trans_smem = 18624 * 4;   // 74496 B dynamic (same as R1/R2 passing config)
    cudaFuncSetAttribute(k_trans, cudaFuncAttributeMaxDynamicSharedMemorySize, trans_smem);

    k_stats_feat<<<4096, 256>>>(a, b, layer_emb, in_proj_w, in_proj_b);
    k_trans<<<64, 512, trans_smem>>>(ln1_g, ln1_b, qkv_w, qkv_b, out_w, out_b,
                                     ln2_g, ln2_b, ffn_w1, ffn_b1, ffn_w2, ffn_b2);
    k_heads<<<512, 256>>>(gate_w, gate_b, row_w, row_b, col_w, col_b,
                          drow_w, drow_b, dcol_w, dcol_b);
    k_merge<<<4096, 256>>>(a, b, delta_scale, out);
}

// round 7
// speedup vs baseline: 1.3551x; 1.0233x over previous
#include <cuda_runtime.h>
#include <math.h>
#include <float.h>

#define FULLMASK 0xffffffffu

#define BB   64
#define HPP  64
#define HH   64
#define WW   64
#define DDIM 32
#define NROW (BB * HPP)   // 4096
#define NEL  (HH * WW)    // 4096

// ---------------- device scratch ----------------
__device__ float g_feat[NROW * DDIM];
__device__ float g_gate[NROW];
__device__ float g_row [NROW * HH];
__device__ float g_col [NROW * WW];
__device__ float g_drow[NROW * HH];
__device__ float g_dcol[NROW * WW];

// ---------------- warp helpers ----------------
__device__ __forceinline__ float wsum(float v) {
#pragma unroll
    for (int m = 16; m > 0; m >>= 1) v += __shfl_xor_sync(FULLMASK, v, m);
    return v;
}
__device__ __forceinline__ float wmaxr(float v) {
#pragma unroll
    for (int m = 16; m > 0; m >>= 1) v = fmaxf(v, __shfl_xor_sync(FULLMASK, v, m));
    return v;
}
__device__ __forceinline__ float wminr(float v) {
#pragma unroll
    for (int m = 16; m > 0; m >>= 1) v = fminf(v, __shfl_xor_sync(FULLMASK, v, m));
    return v;
}

// =====================================================================
// Kernel 1: block-per-row stats. 4096 blocks x 256 threads.
// Each thread: 8 independent float4 loads (MLP_p1=8), 16 elements.
// Streams a,b rows 0..4095 in order -> L2 holds the TAIL afterwards.
// =====================================================================
__global__ void __launch_bounds__(256) k_stats_feat(
        const float* __restrict__ a, const float* __restrict__ b,
        const float* __restrict__ layer_emb,
        const float* __restrict__ ipw, const float* __restrict__ ipb)
{
    const int row = blockIdx.x;
    const int t   = threadIdx.x;
    const int warp = t >> 5;
    const int lane = t & 31;

    const float4* ap = reinterpret_cast<const float4*>(a) + (size_t)row * (NEL / 4);
    const float4* bp = reinterpret_cast<const float4*>(b) + (size_t)row * (NEL / 4);

    // 8 independent loads, front-batched
    float4 A0 = ap[t];        float4 A1 = ap[t + 256];
    float4 A2 = ap[t + 512];  float4 A3 = ap[t + 768];
    float4 B0 = bp[t];        float4 B1 = bp[t + 256];
    float4 B2 = bp[t + 512];  float4 B3 = bp[t + 768];

    float sa = 0.f, sa2 = 0.f, sb = 0.f, sb2 = 0.f, sab = 0.f;
    float mna = FLT_MAX, mxa = -FLT_MAX, mnb = FLT_MAX, mxb = -FLT_MAX;

#define ACC(av, bv, c) { float xa = av.c, xb = bv.c;                        \
        sa += xa; sa2 = fmaf(xa, xa, sa2);                                  \
        sb += xb; sb2 = fmaf(xb, xb, sb2);                                  \
        sab = fmaf(xa, xb, sab);                                            \
        mna = fminf(mna, xa); mxa = fmaxf(mxa, xa);                         \
        mnb = fminf(mnb, xb); mxb = fmaxf(mxb, xb); }
#define ACC4(av, bv) ACC(av, bv, x) ACC(av, bv, y) ACC(av, bv, z) ACC(av, bv, w)
    ACC4(A0, B0) ACC4(A1, B1) ACC4(A2, B2) ACC4(A3, B3)
#undef ACC4
#undef ACC

    sa  = wsum(sa);  sa2 = wsum(sa2);
    sb  = wsum(sb);  sb2 = wsum(sb2);
    sab = wsum(sab);
    mna = wminr(mna); mxa = wmaxr(mxa);
    mnb = wminr(mnb); mxb = wmaxr(mxb);

    __shared__ float red[9][8];
    if (lane == 0) {
        red[0][warp] = sa;  red[1][warp] = sa2;
        red[2][warp] = sb;  red[3][warp] = sb2;
        red[4][warp] = sab;
        red[5][warp] = mna; red[6][warp] = mxa;
        red[7][warp] = mnb; red[8][warp] = mxb;
    }
    __syncthreads();

    if (warp == 0) {
        bool ok = lane < 8;
        float v_sa  = ok ? red[0][lane] : 0.f;
        float v_sa2 = ok ? red[1][lane] : 0.f;
        float v_sb  = ok ? red[2][lane] : 0.f;
        float v_sb2 = ok ? red[3][lane] : 0.f;
        float v_sab = ok ? red[4][lane] : 0.f;
        float v_mna = ok ? red[5][lane] :  FLT_MAX;
        float v_mxa = ok ? red[6][lane] : -FLT_MAX;
        float v_mnb = ok ? red[7][lane] :  FLT_MAX;
        float v_mxb = ok ? red[8][lane] : -FLT_MAX;

        v_sa  = wsum(v_sa);  v_sa2 = wsum(v_sa2);
        v_sb  = wsum(v_sb);  v_sb2 = wsum(v_sb2);
        v_sab = wsum(v_sab);
        v_mna = wminr(v_mna); v_mxa = wmaxr(v_mxa);
        v_mnb = wminr(v_mnb); v_mxb = wmaxr(v_mxb);

        const float iN   = 1.f / 4096.f;
        const float iNm1 = 1.f / 4095.f;
        const float va  = fmaxf(v_sa2 - v_sa * v_sa * iN, 0.f) * iNm1;
        const float vb  = fmaxf(v_sb2 - v_sb * v_sb * iN, 0.f) * iNm1;
        const float na  = sqrtf(v_sa2);
        const float nb  = sqrtf(v_sb2);
        const float sd  = v_sa - v_sb;
        const float sd2 = fmaxf(v_sa2 - 2.f * v_sab + v_sb2, 0.f);
        const float vd  = fmaxf(sd2 - sd * sd * iN, 0.f) * iNm1;

        float st[12];
        st[0]  = v_sa * iN;  st[1]  = sqrtf(va);
        st[2]  = v_mna;      st[3]  = v_mxa;
        st[4]  = v_sb * iN;  st[5]  = sqrtf(vb);
        st[6]  = v_mnb;      st[7]  = v_mxb;
        st[8]  = sd * iN;    st[9]  = sqrtf(vd);
        st[10] = sqrtf(sd2);
        st[11] = v_sab / (fmaxf(na, 1e-8f) * fmaxf(nb, 1e-8f));

        float f = ipb[lane] + layer_emb[lane];
#pragma unroll
        for (int k = 0; k < 12; k++) f = fmaf(st[k], ipw[lane * 12 + k], f);
        g_feat[row * DDIM + lane] = f;
    }
}

// =====================================================================
// Kernel 2: fused attn + FFN per batch. 64 blocks x 512 threads.
// feat stays in smem across the whole transformer body.
// s_h aliases s_attn -> 74496 B dynamic.
// =====================================================================
__global__ void __launch_bounds__(512) k_trans(
        const float* __restrict__ ln1_g, const float* __restrict__ ln1_b,
        const float* __restrict__ qkv_w, const float* __restrict__ qkv_b,
        const float* __restrict__ out_w, const float* __restrict__ out_b,
        const float* __restrict__ ln2_g, const float* __restrict__ ln2_b,
        const float* __restrict__ w1, const float* __restrict__ b1,
        const float* __restrict__ w2, const float* __restrict__ b2)
{
    extern __shared__ float sm[];
    float* s_feat = sm;            // [64][33]  2112
    float* s_x    = sm + 2112;     // [64][33]  2112
    float* s_qkv  = sm + 4224;     // [64][97]  6208
    float* s_attn = sm + 10432;    // [2][64][64] 8192
    float* s_h    = sm + 10432;    // [64][65]  4160, ALIASES s_attn (dead)
                                   // total 18624 floats = 74496 B

    const int tid  = threadIdx.x;
    const int warp = tid >> 5;
    const int lane = tid & 31;
    const int rbase = blockIdx.x * 64;

    // load feat
    for (int idx = tid; idx < 64 * 32; idx += 512)
        s_feat[(idx >> 5) * 33 + (idx & 31)] = g_feat[rbase * 32 + idx];
    __syncthreads();

    // LN1
    for (int r = warp; r < 64; r += 16) {
        float v  = s_feat[r * 33 + lane];
        float mu = wsum(v) * (1.f / 32.f);
        float d  = v - mu;
        float var = wsum(d * d) * (1.f / 32.f);
        s_x[r * 33 + lane] = d * rsqrtf(var + 1e-5f) * ln1_g[lane] + ln1_b[lane];
    }
    __syncthreads();

    // QKV with register-cached x row
    {
        const int hp = tid & 63;
        const int g  = tid >> 6;          // 0..7
        float xr[32];
#pragma unroll
        for (int d = 0; d < 32; d++) xr[d] = s_x[hp * 33 + d];
#pragma unroll
        for (int c = 0; c < 12; c++) {
            int e = g * 12 + c;           // 0..95
            float acc = qkv_b[e];
#pragma unroll
            for (int d = 0; d < 32; d++)
                acc = fmaf(xr[d], qkv_w[e * 32 + d], acc);
            s_qkv[hp * 97 + e] = acc;
        }
    }
    __syncthreads();

    // scores
    for (int idx = tid; idx < 2 * 64 * 64; idx += 512) {
        int k = idx & 63, q = (idx >> 6) & 63, h = idx >> 12;
        const float* qp = &s_qkv[q * 97 + h * 16];
        const float* kp = &s_qkv[k * 97 + 32 + h * 16];
        float acc = 0.f;
#pragma unroll
        for (int dh = 0; dh < 16; dh++) acc = fmaf(qp[dh], kp[dh], acc);
        s_attn[idx] = acc * 0.25f;
    }
    __syncthreads();

    // softmax
    for (int r = warp; r < 128; r += 16) {
        float* sr = &s_attn[r * 64];
        float s0 = sr[lane], s1 = sr[lane + 32];
        float M  = wmaxr(fmaxf(s0, s1));
        float e0 = __expf(s0 - M), e1 = __expf(s1 - M);
        float inv = 1.f / wsum(e0 + e1);
        sr[lane] = e0 * inv; sr[lane + 32] = e1 * inv;
    }
    __syncthreads();

    // ao -> s_x
    for (int hp = warp; hp < 64; hp += 16) {
        int h = lane >> 4;
        const float* ar = &s_attn[(h << 12) + hp * 64];
        float acc = 0.f;
#pragma unroll
        for (int k = 0; k < 64; k++)
            acc = fmaf(ar[k], s_qkv[k * 97 + 64 + lane], acc);
        s_x[hp * 33 + lane] = acc;
    }
    __syncthreads();

    // out proj + residual (in smem)
    for (int idx = tid; idx < 64 * 32; idx += 512) {
        int d = idx >> 6, hp = idx & 63;
        float acc = out_b[d];
#pragma unroll
        for (int e = 0; e < 32; e++)
            acc = fmaf(s_x[hp * 33 + e], out_w[d * 32 + e], acc);
        s_feat[hp * 33 + d] += acc;
    }
    __syncthreads();

    // LN2 -> s_x
    for (int r = warp; r < 64; r += 16) {
        float v  = s_feat[r * 33 + lane];
        float mu = wsum(v) * (1.f / 32.f);
        float d  = v - mu;
        float var = wsum(d * d) * (1.f / 32.f);
        s_x[r * 33 + lane] = d * rsqrtf(var + 1e-5f) * ln2_g[lane] + ln2_b[lane];
    }
    __syncthreads();

    // FFN1 + exact GELU  (s_attn is dead; s_h aliases it)
    for (int idx = tid; idx < 64 * 64; idx += 512) {
        int f = idx >> 6, r = idx & 63;
        float acc = b1[f];
#pragma unroll
        for (int d = 0; d < 32; d++)
            acc = fmaf(s_x[r * 33 + d], w1[f * 32 + d], acc);
        s_h[r * 65 + f] = 0.5f * acc * (1.f + erff(acc * 0.70710678118654752f));
    }
    __syncthreads();

    // FFN2 + residual
    for (int idx = tid; idx < 64 * 32; idx += 512) {
        int d = idx >> 6, r = idx & 63;
        float acc = b2[d];
#pragma unroll
        for (int f = 0; f < 64; f++)
            acc = fmaf(s_h[r * 65 + f], w2[d * 64 + f], acc);
        s_feat[r * 33 + d] += acc;
    }
    __syncthreads();

    // write final feat
    for (int idx = tid; idx < 64 * 32; idx += 512)
        g_feat[rbase * 32 + idx] = s_feat[(idx >> 5) * 33 + (idx & 31)];
}

// =====================================================================
// Kernel 3: heads. 512 blocks x 256 threads, warp-per-row.
// =====================================================================
__global__ void __launch_bounds__(256) k_heads(
        const float* __restrict__ gate_w, const float* __restrict__ gate_b,
        const float* __restrict__ row_w,  const float* __restrict__ row_b,
        const float* __restrict__ col_w,  const float* __restrict__ col_b,
        const float* __restrict__ drow_w, const float* __restrict__ drow_b,
        const float* __restrict__ dcol_w, const float* __restrict__ dcol_b)
{
    __shared__ float s_w[4][32 * 65];   // transposed [d][i], pad 65
    __shared__ float s_bias[4][64];
    __shared__ float s_gw[32];

    const int tid  = threadIdx.x;
    const int warp = tid >> 5;
    const int lane = tid & 31;

    const float* wsrc[4] = { row_w, col_w, drow_w, dcol_w };
    const float* bsrc[4] = { row_b, col_b, drow_b, dcol_b };

    for (int idx = tid; idx < 4 * 64 * 32; idx += 256) {
        int h = idx >> 11, rem = idx & 2047;
        int i = rem >> 5, d = rem & 31;
        s_w[h][d * 65 + i] = wsrc[h][i * 32 + d];
    }
    for (int idx = tid; idx < 256; idx += 256) {
        int h = idx >> 6, i = idx & 63;
        s_bias[h][i] = bsrc[h][i];
    }
    if (tid < 32) s_gw[tid] = gate_w[tid];
    __syncthreads();

    const int rw = blockIdx.x * 8 + warp;  // row, < 4096
    float f = g_feat[rw * 32 + lane];

    float a0 = s_bias[0][lane], a1 = s_bias[0][lane + 32];
    float c0 = s_bias[1][lane], c1 = s_bias[1][lane + 32];
    float p0 = s_bias[2][lane], p1 = s_bias[2][lane + 32];
    float q0 = s_bias[3][lane], q1 = s_bias[3][lane + 32];
    float gacc = 0.f;

#pragma unroll
    for (int d = 0; d < 32; d++) {
        float fd = __shfl_sync(FULLMASK, f, d);
        a0 = fmaf(fd, s_w[0][d * 65 + lane],      a0);
        a1 = fmaf(fd, s_w[0][d * 65 + lane + 32], a1);
        c0 = fmaf(fd, s_w[1][d * 65 + lane],      c0);
        c1 = fmaf(fd, s_w[1][d * 65 + lane + 32], c1);
        p0 = fmaf(fd, s_w[2][d * 65 + lane],      p0);
        p1 = fmaf(fd, s_w[2][d * 65 + lane + 32], p1);
        q0 = fmaf(fd, s_w[3][d * 65 + lane],      q0);
        q1 = fmaf(fd, s_w[3][d * 65 + lane + 32], q1);
        gacc = fmaf(fd, s_gw[d], gacc);
    }

    g_row [rw * 64 + lane] = a0;  g_row [rw * 64 + lane + 32] = a1;
    g_col [rw * 64 + lane] = c0;  g_col [rw * 64 + lane + 32] = c1;
    g_drow[rw * 64 + lane] = p0;  g_drow[rw * 64 + lane + 32] = p1;
    g_dcol[rw * 64 + lane] = q0;  g_dcol[rw * 64 + lane + 32] = q1;
    if (lane == 0) g_gate[rw] = gacc + gate_b[0];
}

// =====================================================================
// Kernel 4: merge, REVERSE block order. 4096 blocks x 256 threads.
// k_stats streamed rows 0->4095; L2 (126MB) holds the ~last 3800 rows
// of a,b (134MB total). Reading 4095->0 harvests that residue instead
// of LRU-thrashing it. Semantically a pure block-index remap.
// =====================================================================
__global__ void __launch_bounds__(256) k_merge(
        const float* __restrict__ a, const float* __restrict__ b,
        const float* __restrict__ ds_p, float* __restrict__ out)
{
    __shared__ float sA[64], sC[64], sDr[64], sDc[64];
    const int blk = (NROW - 1) - blockIdx.x;   // reverse order
    const int t   = threadIdx.x;

    if (t < 64) {
        float g  = g_gate[blk];
        float rv = fminf(fmaxf(g + g_row[blk * 64 + t], -25.f), 25.f);
        float cv = fminf(fmaxf(g_col[blk * 64 + t],     -25.f), 25.f);
        sA[t]  = __expf(rv);
        sC[t]  = __expf(cv);
        sDr[t] = ds_p[0] * g_drow[blk * 64 + t];
        sDc[t] = g_dcol[blk * 64 + t];
    }
    __syncthreads();

    const float4* ap = reinterpret_cast<const float4*>(a) + (size_t)blk * 1024;
    const float4* bp = reinterpret_cast<const float4*>(b) + (size_t)blk * 1024;
    float4*       op = reinterpret_cast<float4*>(out)     + (size_t)blk * 1024;

#pragma unroll
    for (int rep = 0; rep < 4; rep++) {
        int f = t + rep * 256;
        float4 av = __ldcs(ap + f);
        float4 bv = __ldcs(bp + f);
        int i  = f >> 4;
        int jb = (f & 15) << 2;
        float Ai  = sA[i];
        float dri = sDr[i];
        float4 o;
#define MERGE(c, jj) {                                                      \
            float E = Ai * sC[jj];                                          \
            float m = __fdividef(E, 1.f + E);                               \
            o.c = fmaf(m, av.c - bv.c, fmaf(dri, sDc[jj], bv.c)); }
        MERGE(x, jb + 0) MERGE(y, jb + 1) MERGE(z, jb + 2) MERGE(w, jb + 3)
#undef MERGE
        __stcs(op + f, o);
    }
}

// =====================================================================
// launcher
// =====================================================================
extern "C" void kernel_launch(void* const* d_in, const int* in_sizes, int n_in,
                              void* d_out, int out_size)
{
    const float* a           = (const float*)d_in[0];
    const float* b           = (const float*)d_in[1];
    const float* layer_emb   = (const float*)d_in[2];
    const float* in_proj_w   = (const float*)d_in[3];
    const float* in_proj_b   = (const float*)d_in[4];
    const float* ln1_g       = (const float*)d_in[5];
    const float* ln1_b       = (const float*)d_in[6];
    const float* qkv_w       = (const float*)d_in[7];
    const float* qkv_b       = (const float*)d_in[8];
    const float* out_w       = (const float*)d_in[9];
    const float* out_b       = (const float*)d_in[10];
    const float* ln2_g       = (const float*)d_in[11];
    const float* ln2_b       = (const float*)d_in[12];
    const float* ffn_w1      = (const float*)d_in[13];
    const float* ffn_b1      = (const float*)d_in[14];
    const float* ffn_w2      = (const float*)d_in[15];
    const float* ffn_b2      = (const float*)d_in[16];
    const float* gate_w      = (const float*)d_in[17];
    const float* gate_b      = (const float*)d_in[18];
    const float* row_w       = (const float*)d_in[19];
    const float* row_b       = (const float*)d_in[20];
    const float* col_w       = (const float*)d_in[21];
    const float* col_b       = (const float*)d_in[22];
    const float* drow_w      = (const float*)d_in[23];
    const float* drow_b      = (const float*)d_in[24];
    const float* dcol_w      = (const float*)d_in[25];
    const float* dcol_b      = (const float*)d_in[26];
    const float* delta_scale = (const float*)d_in[27];
    float* out = (float*)d_out;

    const int trans_smem = 18624 * 4;   // 74496 B dynamic
    cudaFuncSetAttribute(k_trans, cudaFuncAttributeMaxDynamicSharedMemorySize, trans_smem);

    k_stats_feat<<<4096, 256>>>(a, b, layer_emb, in_proj_w, in_proj_b);
    k_trans<<<64, 512, trans_smem>>>(ln1_g, ln1_b, qkv_w, qkv_b, out_w, out_b,
                                     ln2_g, ln2_b, ffn_w1, ffn_b1, ffn_w2, ffn_b2);
    k_heads<<<512, 256>>>(gate_w, gate_b, row_w, row_b, col_w, col_b,
                          drow_w, drow_b, dcol_w, dcol_b);
    k_merge<<<4096, 256>>>(a, b, delta_scale, out);
}

// round 10
// speedup vs baseline: 1.5356x; 1.1332x over previous
#include <cuda_runtime.h>
#include <math.h>
#include <float.h>

#define FULLMASK 0xffffffffu

#define BB   64
#define HPP  64
#define HH   64
#define WW   64
#define DDIM 32
#define NROW (BB * HPP)   // 4096
#define NEL  (HH * WW)    // 4096

// ---------------- device scratch ----------------
__device__ float g_feat[NROW * DDIM];
__device__ float g_gate[NROW];
__device__ float g_row [NROW * HH];
__device__ float g_col [NROW * WW];
__device__ float g_drow[NROW * HH];
__device__ float g_dcol[NROW * WW];

// ---------------- warp helpers ----------------
__device__ __forceinline__ float wsum(float v) {
#pragma unroll
    for (int m = 16; m > 0; m >>= 1) v += __shfl_xor_sync(FULLMASK, v, m);
    return v;
}
__device__ __forceinline__ float wmaxr(float v) {
#pragma unroll
    for (int m = 16; m > 0; m >>= 1) v = fmaxf(v, __shfl_xor_sync(FULLMASK, v, m));
    return v;
}
__device__ __forceinline__ float wminr(float v) {
#pragma unroll
    for (int m = 16; m > 0; m >>= 1) v = fminf(v, __shfl_xor_sync(FULLMASK, v, m));
    return v;
}

// vectorized global->smem copy (n must be a multiple of 4)
__device__ __forceinline__ void cpy4(float* dst, const float* __restrict__ src,
                                     int n, int tid, int nt) {
    const float4* s = reinterpret_cast<const float4*>(src);
    float4*       d = reinterpret_cast<float4*>(dst);
    for (int i = tid; i < (n >> 2); i += nt) d[i] = s[i];
}

// =====================================================================
// Kernel 1: block-per-row stats. 4096 blocks x 256 threads. (unchanged)
// =====================================================================
__global__ void __launch_bounds__(256) k_stats_feat(
        const float* __restrict__ a, const float* __restrict__ b,
        const float* __restrict__ layer_emb,
        const float* __restrict__ ipw, const float* __restrict__ ipb)
{
    const int row = blockIdx.x;
    const int t   = threadIdx.x;
    const int warp = t >> 5;
    const int lane = t & 31;

    const float4* ap = reinterpret_cast<const float4*>(a) + (size_t)row * (NEL / 4);
    const float4* bp = reinterpret_cast<const float4*>(b) + (size_t)row * (NEL / 4);

    float4 A0 = ap[t];        float4 A1 = ap[t + 256];
    float4 A2 = ap[t + 512];  float4 A3 = ap[t + 768];
    float4 B0 = bp[t];        float4 B1 = bp[t + 256];
    float4 B2 = bp[t + 512];  float4 B3 = bp[t + 768];

    float sa = 0.f, sa2 = 0.f, sb = 0.f, sb2 = 0.f, sab = 0.f;
    float mna = FLT_MAX, mxa = -FLT_MAX, mnb = FLT_MAX, mxb = -FLT_MAX;

#define ACC(av, bv, c) { float xa = av.c, xb = bv.c;                        \
        sa += xa; sa2 = fmaf(xa, xa, sa2);                                  \
        sb += xb; sb2 = fmaf(xb, xb, sb2);                                  \
        sab = fmaf(xa, xb, sab);                                            \
        mna = fminf(mna, xa); mxa = fmaxf(mxa, xa);                         \
        mnb = fminf(mnb, xb); mxb = fmaxf(mxb, xb); }
#define ACC4(av, bv) ACC(av, bv, x) ACC(av, bv, y) ACC(av, bv, z) ACC(av, bv, w)
    ACC4(A0, B0) ACC4(A1, B1) ACC4(A2, B2) ACC4(A3, B3)
#undef ACC4
#undef ACC

    sa  = wsum(sa);  sa2 = wsum(sa2);
    sb  = wsum(sb);  sb2 = wsum(sb2);
    sab = wsum(sab);
    mna = wminr(mna); mxa = wmaxr(mxa);
    mnb = wminr(mnb); mxb = wmaxr(mxb);

    __shared__ float red[9][8];
    if (lane == 0) {
        red[0][warp] = sa;  red[1][warp] = sa2;
        red[2][warp] = sb;  red[3][warp] = sb2;
        red[4][warp] = sab;
        red[5][warp] = mna; red[6][warp] = mxa;
        red[7][warp] = mnb; red[8][warp] = mxb;
    }
    __syncthreads();

    if (warp == 0) {
        bool ok = lane < 8;
        float v_sa  = ok ? red[0][lane] : 0.f;
        float v_sa2 = ok ? red[1][lane] : 0.f;
        float v_sb  = ok ? red[2][lane] : 0.f;
        float v_sb2 = ok ? red[3][lane] : 0.f;
        float v_sab = ok ? red[4][lane] : 0.f;
        float v_mna = ok ? red[5][lane] :  FLT_MAX;
        float v_mxa = ok ? red[6][lane] : -FLT_MAX;
        float v_mnb = ok ? red[7][lane] :  FLT_MAX;
        float v_mxb = ok ? red[8][lane] : -FLT_MAX;

        v_sa  = wsum(v_sa);  v_sa2 = wsum(v_sa2);
        v_sb  = wsum(v_sb);  v_sb2 = wsum(v_sb2);
        v_sab = wsum(v_sab);
        v_mna = wminr(v_mna); v_mxa = wmaxr(v_mxa);
        v_mnb = wminr(v_mnb); v_mxb = wmaxr(v_mxb);

        const float iN   = 1.f / 4096.f;
        const float iNm1 = 1.f / 4095.f;
        const float va  = fmaxf(v_sa2 - v_sa * v_sa * iN, 0.f) * iNm1;
        const float vb  = fmaxf(v_sb2 - v_sb * v_sb * iN, 0.f) * iNm1;
        const float na  = sqrtf(v_sa2);
        const float nb  = sqrtf(v_sb2);
        const float sd  = v_sa - v_sb;
        const float sd2 = fmaxf(v_sa2 - 2.f * v_sab + v_sb2, 0.f);
        const float vd  = fmaxf(sd2 - sd * sd * iN, 0.f) * iNm1;

        float st[12];
        st[0]  = v_sa * iN;  st[1]  = sqrtf(va);
        st[2]  = v_mna;      st[3]  = v_mxa;
        st[4]  = v_sb * iN;  st[5]  = sqrtf(vb);
        st[6]  = v_mnb;      st[7]  = v_mxb;
        st[8]  = sd * iN;    st[9]  = sqrtf(vd);
        st[10] = sqrtf(sd2);
        st[11] = v_sab / (fmaxf(na, 1e-8f) * fmaxf(nb, 1e-8f));

        float f = ipb[lane] + layer_emb[lane];
#pragma unroll
        for (int k = 0; k < 12; k++) f = fmaf(st[k], ipw[lane * 12 + k], f);
        g_feat[row * DDIM + lane] = f;
    }
}

// =====================================================================
// Kernel 2 v2b: fused attn + FFN per batch. 64 blocks x 512 threads.
// Weights staged into STATIC shared (34176 B); dynamic smem stays at
// the proven 74496 B footprint. Inner loops: LDS.128 instead of LDG.
// =====================================================================
__global__ void __launch_bounds__(512) k_trans(
        const float* __restrict__ ln1_g, const float* __restrict__ ln1_b,
        const float* __restrict__ qkv_w, const float* __restrict__ qkv_b,
        const float* __restrict__ out_w, const float* __restrict__ out_b,
        const float* __restrict__ ln2_g, const float* __restrict__ ln2_b,
        const float* __restrict__ w1, const float* __restrict__ b1,
        const float* __restrict__ w2, const float* __restrict__ b2)
{
    extern __shared__ float sm[];
    float* s_feat = sm;             // [64][33]   2112
    float* s_x    = sm + 2112;      // [64][33]   2112
    float* s_qkv  = sm + 4224;      // [64][97]   6208
    float* s_attn = sm + 10432;     // [2][64][64] 8192
    float* s_h    = sm + 10432;     // [64][65]   4160 (aliases s_attn, dead)
                                    // dynamic total 18624 floats = 74496 B

    // weights in static shared (34176 B)
    __shared__ float s_qkvw[96 * 32];
    __shared__ float s_outw[32 * 32];
    __shared__ float s_w1  [64 * 32];
    __shared__ float s_w2  [32 * 64];
    __shared__ float s_qkvb[96];
    __shared__ float s_outb[32];
    __shared__ float s_b1  [64];
    __shared__ float s_b2  [32];
    __shared__ float s_l1g [32];
    __shared__ float s_l1b [32];
    __shared__ float s_l2g [32];
    __shared__ float s_l2b [32];

    const int tid  = threadIdx.x;
    const int warp = tid >> 5;
    const int lane = tid & 31;
    const int rbase = blockIdx.x * 64;

    // stage weights + feat
    cpy4(s_qkvw, qkv_w, 96 * 32, tid, 512);
    cpy4(s_outw, out_w, 32 * 32, tid, 512);
    cpy4(s_w1,   w1,    64 * 32, tid, 512);
    cpy4(s_w2,   w2,    32 * 64, tid, 512);
    cpy4(s_qkvb, qkv_b, 96, tid, 512);
    cpy4(s_outb, out_b, 32, tid, 512);
    cpy4(s_b1,   b1,    64, tid, 512);
    cpy4(s_b2,   b2,    32, tid, 512);
    cpy4(s_l1g,  ln1_g, 32, tid, 512);
    cpy4(s_l1b,  ln1_b, 32, tid, 512);
    cpy4(s_l2g,  ln2_g, 32, tid, 512);
    cpy4(s_l2b,  ln2_b, 32, tid, 512);
    for (int idx = tid; idx < 64 * 32; idx += 512)
        s_feat[(idx >> 5) * 33 + (idx & 31)] = g_feat[rbase * 32 + idx];
    __syncthreads();

    // LN1
    for (int r = warp; r < 64; r += 16) {
        float v  = s_feat[r * 33 + lane];
        float mu = wsum(v) * (1.f / 32.f);
        float d  = v - mu;
        float var = wsum(d * d) * (1.f / 32.f);
        s_x[r * 33 + lane] = d * rsqrtf(var + 1e-5f) * s_l1g[lane] + s_l1b[lane];
    }
    __syncthreads();

    // QKV: x row in regs, weight rows as float4 LDS (warp-uniform broadcast)
    {
        const int hp = tid & 63;
        const int g  = tid >> 6;          // 0..7
        float xr[32];
#pragma unroll
        for (int d = 0; d < 32; d++) xr[d] = s_x[hp * 33 + d];
        const float4* wq = reinterpret_cast<const float4*>(s_qkvw);
#pragma unroll
        for (int c = 0; c < 12; c++) {
            int e = g * 12 + c;           // 0..95
            float acc = s_qkvb[e];
#pragma unroll
            for (int d4 = 0; d4 < 8; d4++) {
                float4 w = wq[e * 8 + d4];
                acc = fmaf(xr[d4 * 4 + 0], w.x, acc);
                acc = fmaf(xr[d4 * 4 + 1], w.y, acc);
                acc = fmaf(xr[d4 * 4 + 2], w.z, acc);
                acc = fmaf(xr[d4 * 4 + 3], w.w, acc);
            }
            s_qkv[hp * 97 + e] = acc;
        }
    }
    __syncthreads();

    // scores: thread = (q, h, ksub); q-row cached in regs, kp warp-uniform
    {
        const int q   = tid & 63;
        const int h   = (tid >> 6) & 1;
        const int sub = tid >> 7;         // 0..3
        float qr[16];
#pragma unroll
        for (int dh = 0; dh < 16; dh++) qr[dh] = s_qkv[q * 97 + h * 16 + dh];
#pragma unroll
        for (int kk = 0; kk < 16; kk++) {
            int k = sub * 16 + kk;
            const float* kp = &s_qkv[k * 97 + 32 + h * 16];
            float acc = 0.f;
#pragma unroll
            for (int dh = 0; dh < 16; dh++) acc = fmaf(qr[dh], kp[dh], acc);
            s_attn[(h << 12) + q * 64 + k] = acc * 0.25f;
        }
    }
    __syncthreads();

    // softmax
    for (int r = warp; r < 128; r += 16) {
        float* sr = &s_attn[r * 64];
        float s0 = sr[lane], s1 = sr[lane + 32];
        float M  = wmaxr(fmaxf(s0, s1));
        float e0 = __expf(s0 - M), e1 = __expf(s1 - M);
        float inv = 1.f / wsum(e0 + e1);
        sr[lane] = e0 * inv; sr[lane + 32] = e1 * inv;
    }
    __syncthreads();

    // ao -> s_x (attn read warp-uniform, v read lane-contiguous)
    for (int hp = warp; hp < 64; hp += 16) {
        int h = lane >> 4;
        const float* ar = &s_attn[(h << 12) + hp * 64];
        float acc = 0.f;
#pragma unroll
        for (int k = 0; k < 64; k++)
            acc = fmaf(ar[k], s_qkv[k * 97 + 64 + lane], acc);
        s_x[hp * 33 + lane] = acc;
    }
    __syncthreads();

    // out proj + residual; weight rows float4 from smem
    {
        const float4* wo = reinterpret_cast<const float4*>(s_outw);
        for (int idx = tid; idx < 64 * 32; idx += 512) {
            int d = idx >> 6, hp = idx & 63;
            float acc = s_outb[d];
#pragma unroll
            for (int e4 = 0; e4 < 8; e4++) {
                float4 w = wo[d * 8 + e4];
                acc = fmaf(s_x[hp * 33 + e4 * 4 + 0], w.x, acc);
                acc = fmaf(s_x[hp * 33 + e4 * 4 + 1], w.y, acc);
                acc = fmaf(s_x[hp * 33 + e4 * 4 + 2], w.z, acc);
                acc = fmaf(s_x[hp * 33 + e4 * 4 + 3], w.w, acc);
            }
            s_feat[hp * 33 + d] += acc;
        }
    }
    __syncthreads();

    // LN2 -> s_x
    for (int r = warp; r < 64; r += 16) {
        float v  = s_feat[r * 33 + lane];
        float mu = wsum(v) * (1.f / 32.f);
        float d  = v - mu;
        float var = wsum(d * d) * (1.f / 32.f);
        s_x[r * 33 + lane] = d * rsqrtf(var + 1e-5f) * s_l2g[lane] + s_l2b[lane];
    }
    __syncthreads();

    // FFN1 + exact GELU (s_h aliases dead s_attn)
    {
        const float4* wf = reinterpret_cast<const float4*>(s_w1);
        for (int idx = tid; idx < 64 * 64; idx += 512) {
            int f = idx >> 6, r = idx & 63;
            float acc = s_b1[f];
#pragma unroll
            for (int d4 = 0; d4 < 8; d4++) {
                float4 w = wf[f * 8 + d4];
                acc = fmaf(s_x[r * 33 + d4 * 4 + 0], w.x, acc);
                acc = fmaf(s_x[r * 33 + d4 * 4 + 1], w.y, acc);
                acc = fmaf(s_x[r * 33 + d4 * 4 + 2], w.z, acc);
                acc = fmaf(s_x[r * 33 + d4 * 4 + 3], w.w, acc);
            }
            s_h[r * 65 + f] = 0.5f * acc * (1.f + erff(acc * 0.70710678118654752f));
        }
    }
    __syncthreads();

    // FFN2 + residual
    {
        const float4* wf = reinterpret_cast<const float4*>(s_w2);
        for (int idx = tid; idx < 64 * 32; idx += 512) {
            int d = idx >> 6, r = idx & 63;
            float acc = s_b2[d];
#pragma unroll
            for (int f4 = 0; f4 < 16; f4++) {
                float4 w = wf[d * 16 + f4];
                acc = fmaf(s_h[r * 65 + f4 * 4 + 0], w.x, acc);
                acc = fmaf(s_h[r * 65 + f4 * 4 + 1], w.y, acc);
                acc = fmaf(s_h[r * 65 + f4 * 4 + 2], w.z, acc);
                acc = fmaf(s_h[r * 65 + f4 * 4 + 3], w.w, acc);
            }
            s_feat[r * 33 + d] += acc;
        }
    }
    __syncthreads();

    // write final feat
    for (int idx = tid; idx < 64 * 32; idx += 512)
        g_feat[rbase * 32 + idx] = s_feat[(idx >> 5) * 33 + (idx & 31)];
}

// =====================================================================
// Kernel 3: heads. 512 blocks x 256 threads, warp-per-row. (unchanged)
// =====================================================================
__global__ void __launch_bounds__(256) k_heads(
        const float* __restrict__ gate_w, const float* __restrict__ gate_b,
        const float* __restrict__ row_w,  const float* __restrict__ row_b,
        const float* __restrict__ col_w,  const float* __restrict__ col_b,
        const float* __restrict__ drow_w, const float* __restrict__ drow_b,
        const float* __restrict__ dcol_w, const float* __restrict__ dcol_b)
{
    __shared__ float s_w[4][32 * 65];
    __shared__ float s_bias[4][64];
    __shared__ float s_gw[32];

    const int tid  = threadIdx.x;
    const int warp = tid >> 5;
    const int lane = tid & 31;

    const float* wsrc[4] = { row_w, col_w, drow_w, dcol_w };
    const float* bsrc[4] = { row_b, col_b, drow_b, dcol_b };

    for (int idx = tid; idx < 4 * 64 * 32; idx += 256) {
        int h = idx >> 11, rem = idx & 2047;
        int i = rem >> 5, d = rem & 31;
        s_w[h][d * 65 + i] = wsrc[h][i * 32 + d];
    }
    for (int idx = tid; idx < 256; idx += 256) {
        int h = idx >> 6, i = idx & 63;
        s_bias[h][i] = bsrc[h][i];
    }
    if (tid < 32) s_gw[tid] = gate_w[tid];
    __syncthreads();

    const int rw = blockIdx.x * 8 + warp;
    float f = g_feat[rw * 32 + lane];

    float a0 = s_bias[0][lane], a1 = s_bias[0][lane + 32];
    float c0 = s_bias[1][lane], c1 = s_bias[1][lane + 32];
    float p0 = s_bias[2][lane], p1 = s_bias[2][lane + 32];
    float q0 = s_bias[3][lane], q1 = s_bias[3][lane + 32];
    float gacc = 0.f;

#pragma unroll
    for (int d = 0; d < 32; d++) {
        float fd = __shfl_sync(FULLMASK, f, d);
        a0 = fmaf(fd, s_w[0][d * 65 + lane],      a0);
        a1 = fmaf(fd, s_w[0][d * 65 + lane + 32], a1);
        c0 = fmaf(fd, s_w[1][d * 65 + lane],      c0);
        c1 = fmaf(fd, s_w[1][d * 65 + lane + 32], c1);
        p0 = fmaf(fd, s_w[2][d * 65 + lane],      p0);
        p1 = fmaf(fd, s_w[2][d * 65 + lane + 32], p1);
        q0 = fmaf(fd, s_w[3][d * 65 + lane],      q0);
        q1 = fmaf(fd, s_w[3][d * 65 + lane + 32], q1);
        gacc = fmaf(fd, s_gw[d], gacc);
    }

    g_row [rw * 64 + lane] = a0;  g_row [rw * 64 + lane + 32] = a1;
    g_col [rw * 64 + lane] = c0;  g_col [rw * 64 + lane + 32] = c1;
    g_drow[rw * 64 + lane] = p0;  g_drow[rw * 64 + lane + 32] = p1;
    g_dcol[rw * 64 + lane] = q0;  g_dcol[rw * 64 + lane + 32] = q1;
    if (lane == 0) g_gate[rw] = gacc + gate_b[0];
}

// =====================================================================
// Kernel 4: merge (reverse order kept). 4096 blocks x 256 threads.
// At the LTS cap (~6.7 TB/s measured) -> structural floor ~29us.
// =====================================================================
__global__ void __launch_bounds__(256) k_merge(
        const float* __restrict__ a, const float* __restrict__ b,
        const float* __restrict__ ds_p, float* __restrict__ out)
{
    __shared__ float sA[64], sC[64], sDr[64], sDc[64];
    const int blk = (NROW - 1) - blockIdx.x;
    const int t   = threadIdx.x;

    if (t < 64) {
        float g  = g_gate[blk];
        float rv = fminf(fmaxf(g + g_row[blk * 64 + t], -25.f), 25.f);
        float cv = fminf(fmaxf(g_col[blk * 64 + t],     -25.f), 25.f);
        sA[t]  = __expf(rv);
        sC[t]  = __expf(cv);
        sDr[t] = ds_p[0] * g_drow[blk * 64 + t];
        sDc[t] = g_dcol[blk * 64 + t];
    }
    __syncthreads();

    const float4* ap = reinterpret_cast<const float4*>(a) + (size_t)blk * 1024;
    const float4* bp = reinterpret_cast<const float4*>(b) + (size_t)blk * 1024;
    float4*       op = reinterpret_cast<float4*>(out)     + (size_t)blk * 1024;

#pragma unroll
    for (int rep = 0; rep < 4; rep++) {
        int f = t + rep * 256;
        float4 av = __ldcs(ap + f);
        float4 bv = __ldcs(bp + f);
        int i  = f >> 4;
        int jb = (f & 15) << 2;
        float Ai  = sA[i];
        float dri = sDr[i];
        float4 o;
#define MERGE(c, jj) {                                                      \
            float E = Ai * sC[jj];                                          \
            float m = __fdividef(E, 1.f + E);                               \
            o.c = fmaf(m, av.c - bv.c, fmaf(dri, sDc[jj], bv.c)); }
        MERGE(x, jb + 0) MERGE(y, jb + 1) MERGE(z, jb + 2) MERGE(w, jb + 3)
#undef MERGE
        __stcs(op + f, o);
    }
}

// =====================================================================
// launcher
// =====================================================================
extern "C" void kernel_launch(void* const* d_in, const int* in_sizes, int n_in,
                              void* d_out, int out_size)
{
    const float* a           = (const float*)d_in[0];
    const float* b           = (const float*)d_in[1];
    const float* layer_emb   = (const float*)d_in[2];
    const float* in_proj_w   = (const float*)d_in[3];
    const float* in_proj_b   = (const float*)d_in[4];
    const float* ln1_g       = (const float*)d_in[5];
    const float* ln1_b       = (const float*)d_in[6];
    const float* qkv_w       = (const float*)d_in[7];
    const float* qkv_b       = (const float*)d_in[8];
    const float* out_w       = (const float*)d_in[9];
    const float* out_b       = (const float*)d_in[10];
    const float* ln2_g       = (const float*)d_in[11];
    const float* ln2_b       = (const float*)d_in[12];
    const float* ffn_w1      = (const float*)d_in[13];
    const float* ffn_b1      = (const float*)d_in[14];
    const float* ffn_w2      = (const float*)d_in[15];
    const float* ffn_b2      = (const float*)d_in[16];
    const float* gate_w      = (const float*)d_in[17];
    const float* gate_b      = (const float*)d_in[18];
    const float* row_w       = (const float*)d_in[19];
    const float* row_b       = (const float*)d_in[20];
    const float* col_w       = (const float*)d_in[21];
    const float* col_b       = (const float*)d_in[22];
    const float* drow_w      = (const float*)d_in[23];
    const float* drow_b      = (const float*)d_in[24];
    const float* dcol_w      = (const float*)d_in[25];
    const float* dcol_b      = (const float*)d_in[26];
    const float* delta_scale = (const float*)d_in[27];
    float* out = (float*)d_out;

    const int trans_smem = 18624 * 4;   // 74496 B dynamic (proven size)
    cudaFuncSetAttribute(k_trans, cudaFuncAttributeMaxDynamicSharedMemorySize, trans_smem);

    k_stats_feat<<<4096, 256>>>(a, b, layer_emb, in_proj_w, in_proj_b);
    k_trans<<<64, 512, trans_smem>>>(ln1_g, ln1_b, qkv_w, qkv_b, out_w, out_b,
                                     ln2_g, ln2_b, ffn_w1, ffn_b1, ffn_w2, ffn_b2);
    k_heads<<<512, 256>>>(gate_w, gate_b, row_w, row_b, col_w, col_b,
                          drow_w, drow_b, dcol_w, dcol_b);
    k_merge<<<4096, 256>>>(a, b, delta_scale, out);
}